// round 1
// baseline (speedup 1.0000x reference)
#include <cuda_runtime.h>
#include <math.h>

// Problem dims
#define BB 64
#define TT 200
#define NS 1024      // num_skills
#define CN 256       // concept_num
#define HH 1024      // hidden
#define G4 4096      // 4*hidden
#define MROWS (BB*TT)   // 12800
#define SPLITK 8
#define KCHUNK (HH/SPLITK)   // 128

// Scratch (device globals -- allocation-free per harness rules)
__device__ float g_kcvec[MROWS * 2 * CN];    // [m][512] masked concat
__device__ float g_nextkc[MROWS * CN];       // [m][256]
__device__ float g_G[MROWS * G4];            // [t][b][4096] precomputed gx + biases
__device__ float g_hseq[MROWS * HH];         // [b][t][1024]
__device__ float g_h[BB * HH];
__device__ float g_c[BB * HH];
__device__ float g_part[SPLITK * BB * G4];   // split-K partials for one step

__global__ void init_hc() {
    int i = blockIdx.x * blockDim.x + threadIdx.x;
    if (i < BB * HH) { g_h[i] = 0.f; g_c[i] = 0.f; }
}

// ---------------------------------------------------------------------------
// Generic NT SGEMM: C[M,N] = A[M,K] @ B[N,K]^T + bias (+bias2), 128x128x16 tile,
// 256 threads, 8x8 register tile per thread.
// mode 0: write g_nextkc          (N=256)
// mode 1: write g_kcvec masked    (N=256, uses resm)
// mode 2: A=g_kcvec, write g_G[t][b] layout (N=4096)
// mode 3: A=g_hseq,  write Cext   (N=256)
// ---------------------------------------------------------------------------
__global__ void sgemm_big(const float* __restrict__ A_,
                          const float* __restrict__ Bm,
                          const float* __restrict__ bias,
                          const float* __restrict__ bias2,
                          float* __restrict__ Cext,
                          int M, int N, int K, int mode,
                          const int* __restrict__ resm) {
    __shared__ float As[16][128];
    __shared__ float Bs[16][128];

    const float* A = A_;
    if (mode == 2) A = g_kcvec;
    else if (mode == 3) A = g_hseq;

    int tid = threadIdx.x;
    int m0 = blockIdx.y * 128;
    int n0 = blockIdx.x * 128;
    int rt = tid >> 4;        // 0..15 -> rows rt*8..rt*8+7
    int ct = tid & 15;        // 0..15 -> cols ct*8..ct*8+7
    int lr = tid >> 2;        // 0..63
    int lk = (tid & 3) * 4;   // 0,4,8,12

    float acc[8][8];
#pragma unroll
    for (int i = 0; i < 8; i++)
#pragma unroll
        for (int j = 0; j < 8; j++) acc[i][j] = 0.f;

    for (int k0 = 0; k0 < K; k0 += 16) {
        float4 a0 = *(const float4*)&A[(size_t)(m0 + lr) * K + k0 + lk];
        float4 a1 = *(const float4*)&A[(size_t)(m0 + lr + 64) * K + k0 + lk];
        float4 b0 = *(const float4*)&Bm[(size_t)(n0 + lr) * K + k0 + lk];
        float4 b1 = *(const float4*)&Bm[(size_t)(n0 + lr + 64) * K + k0 + lk];
        __syncthreads();
        As[lk + 0][lr] = a0.x; As[lk + 1][lr] = a0.y; As[lk + 2][lr] = a0.z; As[lk + 3][lr] = a0.w;
        As[lk + 0][lr + 64] = a1.x; As[lk + 1][lr + 64] = a1.y; As[lk + 2][lr + 64] = a1.z; As[lk + 3][lr + 64] = a1.w;
        Bs[lk + 0][lr] = b0.x; Bs[lk + 1][lr] = b0.y; Bs[lk + 2][lr] = b0.z; Bs[lk + 3][lr] = b0.w;
        Bs[lk + 0][lr + 64] = b1.x; Bs[lk + 1][lr + 64] = b1.y; Bs[lk + 2][lr + 64] = b1.z; Bs[lk + 3][lr + 64] = b1.w;
        __syncthreads();
#pragma unroll
        for (int kk = 0; kk < 16; kk++) {
            float a[8], b[8];
            *(float4*)&a[0] = *(const float4*)&As[kk][rt * 8];
            *(float4*)&a[4] = *(const float4*)&As[kk][rt * 8 + 4];
            *(float4*)&b[0] = *(const float4*)&Bs[kk][ct * 8];
            *(float4*)&b[4] = *(const float4*)&Bs[kk][ct * 8 + 4];
#pragma unroll
            for (int i = 0; i < 8; i++)
#pragma unroll
                for (int j = 0; j < 8; j++) acc[i][j] += a[i] * b[j];
        }
    }

#pragma unroll
    for (int i = 0; i < 8; i++) {
        int m = m0 + rt * 8 + i;
#pragma unroll
        for (int j = 0; j < 8; j++) {
            int n = n0 + ct * 8 + j;
            float v = acc[i][j] + bias[n];
            if (bias2) v += bias2[n];
            if (mode == 0) {
                g_nextkc[m * CN + n] = v;
            } else if (mode == 1) {
                float msk = (resm[m] == 1) ? 1.f : 0.f;
                g_kcvec[m * 2 * CN + n] = v * msk;
                g_kcvec[m * 2 * CN + CN + n] = v * (1.f - msk);
            } else if (mode == 2) {
                int b = m / TT, t = m - b * TT;
                g_G[(t * BB + b) * G4 + n] = v;
            } else {
                Cext[m * CN + n] = v;
            }
        }
    }
}

// ---------------------------------------------------------------------------
// Per-step recurrent GEMM: g_part[s][b][n] = (h @ W_hh^T) partial over K chunk s.
// grid = (16 col-blocks of 256, SPLITK), 256 threads, 8x8 per thread.
// ---------------------------------------------------------------------------
__global__ void lstm_step_gemm(const float* __restrict__ Whh) {
    __shared__ float As[16][64];
    __shared__ float Bs[16][256];

    int tid = threadIdx.x;
    int n0 = blockIdx.x * 256;
    int kb = blockIdx.y * KCHUNK;
    int rt = tid >> 5;        // 0..7  -> rows rt*8..
    int ct = tid & 31;        // 0..31 -> cols ct*8..
    int lr = tid >> 2;        // 0..63
    int lk = (tid & 3) * 4;

    float acc[8][8];
#pragma unroll
    for (int i = 0; i < 8; i++)
#pragma unroll
        for (int j = 0; j < 8; j++) acc[i][j] = 0.f;

    for (int k0 = kb; k0 < kb + KCHUNK; k0 += 16) {
        float4 av = *(const float4*)&g_h[lr * HH + k0 + lk];
        float4 bv[4];
#pragma unroll
        for (int q = 0; q < 4; q++)
            bv[q] = *(const float4*)&Whh[(size_t)(n0 + tid) * HH + k0 + q * 4];
        __syncthreads();
        As[lk + 0][lr] = av.x; As[lk + 1][lr] = av.y; As[lk + 2][lr] = av.z; As[lk + 3][lr] = av.w;
#pragma unroll
        for (int q = 0; q < 4; q++) {
            Bs[q * 4 + 0][tid] = bv[q].x;
            Bs[q * 4 + 1][tid] = bv[q].y;
            Bs[q * 4 + 2][tid] = bv[q].z;
            Bs[q * 4 + 3][tid] = bv[q].w;
        }
        __syncthreads();
#pragma unroll
        for (int kk = 0; kk < 16; kk++) {
            float a[8], b[8];
            *(float4*)&a[0] = *(const float4*)&As[kk][rt * 8];
            *(float4*)&a[4] = *(const float4*)&As[kk][rt * 8 + 4];
            *(float4*)&b[0] = *(const float4*)&Bs[kk][ct * 8];
            *(float4*)&b[4] = *(const float4*)&Bs[kk][ct * 8 + 4];
#pragma unroll
            for (int i = 0; i < 8; i++)
#pragma unroll
                for (int j = 0; j < 8; j++) acc[i][j] += a[i] * b[j];
        }
    }

    float* outp = g_part + (size_t)(blockIdx.y * BB) * G4 + n0;
#pragma unroll
    for (int i = 0; i < 8; i++) {
        int r = rt * 8 + i;
#pragma unroll
        for (int j = 0; j < 8; j++)
            outp[r * G4 + ct * 8 + j] = acc[i][j];
    }
}

// ---------------------------------------------------------------------------
// Gate + state update for step t. 64*1024 threads: (b, j).
// ---------------------------------------------------------------------------
__global__ void lstm_gate(int t) {
    int idx = blockIdx.x * blockDim.x + threadIdx.x;   // b*1024 + j
    int b = idx >> 10, j = idx & 1023;
    const float* Gp = g_G + (size_t)(t * BB + b) * G4;
    float pi = Gp[j];
    float pf = Gp[HH + j];
    float pg = Gp[2 * HH + j];
    float po = Gp[3 * HH + j];
#pragma unroll
    for (int s = 0; s < SPLITK; s++) {
        const float* P = g_part + (size_t)(s * BB + b) * G4;
        pi += P[j]; pf += P[HH + j]; pg += P[2 * HH + j]; po += P[3 * HH + j];
    }
    float iv = 1.f / (1.f + expf(-pi));
    float fv = 1.f / (1.f + expf(-pf));
    float ov = 1.f / (1.f + expf(-po));
    float gv = tanhf(pg);
    float c = fv * g_c[idx] + iv * gv;
    float h = ov * tanhf(c);
    g_c[idx] = c;
    g_h[idx] = h;
    g_hseq[((size_t)b * TT + t) * HH + j] = h;
}

// ---------------------------------------------------------------------------
// Output head: res[m] = sum_c (stu[m,c]-nkc)*nkc*W_out[c] + b_out. One warp/row.
// ---------------------------------------------------------------------------
__global__ void out_kernel(const float* __restrict__ Wout,
                           const float* __restrict__ bout,
                           float* __restrict__ dout) {
    int gw = (blockIdx.x * blockDim.x + threadIdx.x) >> 5;
    int lane = threadIdx.x & 31;
    if (gw >= MROWS) return;
    const float* stu = dout + MROWS + (size_t)gw * CN;
    float s = 0.f;
#pragma unroll
    for (int c = lane; c < CN; c += 32) {
        float nk = g_nextkc[gw * CN + c];
        s += (stu[c] - nk) * nk * Wout[c];
    }
#pragma unroll
    for (int o = 16; o; o >>= 1) s += __shfl_down_sync(0xffffffffu, s, o);
    if (lane == 0) dout[gw] = s + bout[0];
}

extern "C" void kernel_launch(void* const* d_in, const int* in_sizes, int n_in,
                              void* d_out, int out_size) {
    // Input order per reference setup_inputs (concept_num scalar may or may not
    // be materialized as an input -> detect via n_in).
    int wi = (n_in >= 14) ? 4 : 3;
    const float* q_hot   = (const float*)d_in[0];
    const int*   result  = (const int*)  d_in[1];
    const float* next_q  = (const float*)d_in[2];
    const float* W_kc    = (const float*)d_in[wi + 0];
    const float* b_kc    = (const float*)d_in[wi + 1];
    const float* W_ih    = (const float*)d_in[wi + 2];
    const float* W_hh    = (const float*)d_in[wi + 3];
    const float* b_ih    = (const float*)d_in[wi + 4];
    const float* b_hh    = (const float*)d_in[wi + 5];
    const float* W_state = (const float*)d_in[wi + 6];
    const float* b_state = (const float*)d_in[wi + 7];
    const float* W_out   = (const float*)d_in[wi + 8];
    const float* b_out   = (const float*)d_in[wi + 9];
    float* out = (float*)d_out;

    init_hc<<<(BB * HH + 255) / 256, 256>>>();

    dim3 gk(CN / 128, MROWS / 128);       // (2, 100)
    // kc_hot -> masked kc_vec
    sgemm_big<<<gk, 256>>>(q_hot, W_kc, b_kc, nullptr, nullptr,
                           MROWS, CN, NS, 1, result);
    // next_kc_hot
    sgemm_big<<<gk, 256>>>(next_q, W_kc, b_kc, nullptr, nullptr,
                           MROWS, CN, NS, 0, nullptr);
    // gx: kc_vec @ W_ih^T + b_ih + b_hh  -> g_G[t][b][:]
    dim3 gg(G4 / 128, MROWS / 128);       // (32, 100)
    sgemm_big<<<gg, 256>>>(nullptr, W_ih, b_ih, b_hh, nullptr,
                           MROWS, G4, 2 * CN, 2, nullptr);

    // LSTM recurrence
    for (int t = 0; t < TT; t++) {
        lstm_step_gemm<<<dim3(G4 / 256, SPLITK), 256>>>(W_hh);
        lstm_gate<<<(BB * HH) / 256, 256>>>(t);
    }

    // stu_state -> d_out[12800:]
    sgemm_big<<<gk, 256>>>(nullptr, W_state, b_state, nullptr, out + MROWS,
                           MROWS, CN, HH, 3, nullptr);
    // res -> d_out[:12800]
    out_kernel<<<(MROWS * 32 + 255) / 256, 256>>>(W_out, b_out, out);
}

// round 2
// speedup vs baseline: 1.2915x; 1.2915x over previous
#include <cuda_runtime.h>
#include <math.h>

typedef unsigned long long ull;

// Problem dims
#define BB 64
#define TT 200
#define NS 1024      // num_skills
#define CN 256       // concept_num
#define HH 1024      // hidden
#define G4 4096      // 4*hidden
#define MROWS (BB*TT)   // 12800

// Persistent-kernel config
#define NCTA 128
#define KC 128          // K chunk
#define WPITCH 1028     // padded pitch for W_hh smem slice
#define SMEM_P ((32*WPITCH + 2*KC*64) * 4)   // 197120 bytes

// Scratch (device globals -- allocation-free per harness rules)
__device__ float g_kcvec[MROWS * 2 * CN];
__device__ float g_nextkc[MROWS * CN];
__device__ float g_G[(size_t)MROWS * G4];      // [t][b][4096] gx + biases
__device__ float g_hseq[(size_t)MROWS * HH];   // [b][t][1024]
__device__ float g_hb[2][HH * BB];             // h double buffer, layout [j][b]
__device__ unsigned g_barc;

// ---- packed f32x2 helpers (sm_103a) ----
__device__ __forceinline__ ull dup2f(float x) {
    ull r; asm("mov.b64 %0, {%1, %1};" : "=l"(r) : "f"(x)); return r;
}
__device__ __forceinline__ void ffma2(ull& d, ull a, ull b) {
    asm("fma.rn.f32x2 %0, %1, %2, %0;" : "+l"(d) : "l"(a), "l"(b));
}
__device__ __forceinline__ float2 u2f(ull v) {
    float2 f; asm("mov.b64 {%0, %1}, %2;" : "=f"(f.x), "=f"(f.y) : "l"(v)); return f;
}

__global__ void init_misc() {
    int i = blockIdx.x * blockDim.x + threadIdx.x;
    if (i < HH * BB) g_hb[0][i] = 0.f;
    if (i == 0) g_barc = 0u;
}

// ---------------------------------------------------------------------------
// Generic NT SGEMM with FFMA2: C[M,N] = A[M,K] @ B[N,K]^T + bias (+bias2).
// 128x128x16 tile, 256 threads, 8x8 per thread (as 8x4 f32x2 pairs).
// mode 0: write g_nextkc; 1: g_kcvec masked; 2: A=g_kcvec -> g_G[t][b][n];
// mode 3: A=g_hseq -> Cext.
// ---------------------------------------------------------------------------
__global__ __launch_bounds__(256) void sgemm_big(
        const float* __restrict__ A_, const float* __restrict__ Bm,
        const float* __restrict__ bias, const float* __restrict__ bias2,
        float* __restrict__ Cext, int M, int N, int K, int mode,
        const int* __restrict__ resm) {
    __shared__ float As[16][128];
    __shared__ float Bs[16][128];

    const float* A = A_;
    if (mode == 2) A = g_kcvec;
    else if (mode == 3) A = g_hseq;

    int tid = threadIdx.x;
    int m0 = blockIdx.y * 128;
    int n0 = blockIdx.x * 128;
    int rt = tid >> 4;
    int ct = tid & 15;
    int lr = tid >> 2;
    int lk = (tid & 3) * 4;

    ull acc2[8][4];
#pragma unroll
    for (int i = 0; i < 8; i++)
#pragma unroll
        for (int j = 0; j < 4; j++) acc2[i][j] = 0ull;

    for (int k0 = 0; k0 < K; k0 += 16) {
        float4 a0 = *(const float4*)&A[(size_t)(m0 + lr) * K + k0 + lk];
        float4 a1 = *(const float4*)&A[(size_t)(m0 + lr + 64) * K + k0 + lk];
        float4 b0 = *(const float4*)&Bm[(size_t)(n0 + lr) * K + k0 + lk];
        float4 b1 = *(const float4*)&Bm[(size_t)(n0 + lr + 64) * K + k0 + lk];
        __syncthreads();
        As[lk + 0][lr] = a0.x; As[lk + 1][lr] = a0.y; As[lk + 2][lr] = a0.z; As[lk + 3][lr] = a0.w;
        As[lk + 0][lr + 64] = a1.x; As[lk + 1][lr + 64] = a1.y; As[lk + 2][lr + 64] = a1.z; As[lk + 3][lr + 64] = a1.w;
        Bs[lk + 0][lr] = b0.x; Bs[lk + 1][lr] = b0.y; Bs[lk + 2][lr] = b0.z; Bs[lk + 3][lr] = b0.w;
        Bs[lk + 0][lr + 64] = b1.x; Bs[lk + 1][lr + 64] = b1.y; Bs[lk + 2][lr + 64] = b1.z; Bs[lk + 3][lr + 64] = b1.w;
        __syncthreads();
#pragma unroll
        for (int kk = 0; kk < 16; kk++) {
            float a[8];
            *(float4*)&a[0] = *(const float4*)&As[kk][rt * 8];
            *(float4*)&a[4] = *(const float4*)&As[kk][rt * 8 + 4];
            ull b2[4];
#pragma unroll
            for (int j = 0; j < 4; j++)
                b2[j] = *(const ull*)&Bs[kk][ct * 8 + 2 * j];
#pragma unroll
            for (int i = 0; i < 8; i++) {
                ull ad = dup2f(a[i]);
#pragma unroll
                for (int j = 0; j < 4; j++) ffma2(acc2[i][j], ad, b2[j]);
            }
        }
    }

#pragma unroll
    for (int i = 0; i < 8; i++) {
        int m = m0 + rt * 8 + i;
#pragma unroll
        for (int j = 0; j < 4; j++) {
            float2 p = u2f(acc2[i][j]);
            float pv[2] = {p.x, p.y};
#pragma unroll
            for (int u = 0; u < 2; u++) {
                int n = n0 + ct * 8 + 2 * j + u;
                float v = pv[u] + bias[n];
                if (bias2) v += bias2[n];
                if (mode == 0) {
                    g_nextkc[m * CN + n] = v;
                } else if (mode == 1) {
                    float msk = (resm[m] == 1) ? 1.f : 0.f;
                    g_kcvec[m * 2 * CN + n] = v * msk;
                    g_kcvec[m * 2 * CN + CN + n] = v * (1.f - msk);
                } else if (mode == 2) {
                    int b = m / TT, t = m - b * TT;
                    g_G[((size_t)t * BB + b) * G4 + n] = v;
                } else {
                    Cext[m * CN + n] = v;
                }
            }
        }
    }
}

// ---------------------------------------------------------------------------
// Persistent fused LSTM: 128 CTAs, CTA k owns hidden units [8k, 8k+8).
// W_hh slice (32 rows x 1024) lives in SMEM for the whole kernel.
// Per step: z = h @ Whh_slice^T (double-buffered h chunks), gates, h write,
// grid-wide software barrier.
// ---------------------------------------------------------------------------
__device__ __forceinline__ void gsync(unsigned target) {
    __threadfence();
    __syncthreads();
    if (threadIdx.x == 0) {
        atomicAdd(&g_barc, 1u);
        while (atomicAdd(&g_barc, 0u) < target) { __nanosleep(32); }
    }
    __syncthreads();
}

__global__ __launch_bounds__(256, 1) void lstm_persist(const float* __restrict__ Whh) {
    extern __shared__ float sm[];
    float* Whh_s = sm;                        // [32][WPITCH]
    float* hb0 = sm + 32 * WPITCH;            // [KC][64]
    float* hb1 = hb0 + KC * 64;
    float* zs = hb0;                          // reuse: [64][33]

    const int tid = threadIdx.x;
    const int jb0 = blockIdx.x * 8;

    // Load W_hh slice: col c (0..31) -> global row (c>>3)*1024 + jb0 + (c&7)
    for (int idx = tid * 4; idx < 32 * 1024; idx += 256 * 4) {
        int c = idx >> 10, k = idx & 1023;
        int gr = ((c >> 3) << 10) + jb0 + (c & 7);
        *(float4*)&Whh_s[c * WPITCH + k] = *(const float4*)&Whh[(size_t)gr * HH + k];
    }
    __syncthreads();

    const int rb = tid >> 4;       // 0..15: rows rb*4 .. rb*4+3
    const int cb = tid & 15;       // cols cb and cb+16
    const int b0 = tid & 63;       // gate-phase batch
    const int jl0 = tid >> 6;      // gate-phase j (0..3; +4 for 2nd elem)

    float cst0 = 0.f, cst1 = 0.f;

    for (int t = 0; t < TT; t++) {
        const float* hsrc = g_hb[t & 1];
        float* hdst = g_hb[(t + 1) & 1];
        ull acc00 = 0, acc01 = 0, acc10 = 0, acc11 = 0;

        // preload chunk 0
        float4 r[8];
#pragma unroll
        for (int q = 0; q < 8; q++)
            r[q] = __ldcg((const float4*)&hsrc[q * 1024 + tid * 4]);
        __syncthreads();
#pragma unroll
        for (int q = 0; q < 8; q++)
            *(float4*)&hb0[q * 1024 + tid * 4] = r[q];
        __syncthreads();

        for (int ch = 0; ch < 8; ch++) {
            const float* hs = (ch & 1) ? hb1 : hb0;
            if (ch < 7) {
#pragma unroll
                for (int q = 0; q < 8; q++)
                    r[q] = __ldcg((const float4*)&hsrc[(ch + 1) * 8192 + q * 1024 + tid * 4]);
            }
            const int kbase = ch * KC;
#pragma unroll 4
            for (int kk = 0; kk < KC; kk += 4) {
                float4 w0 = *(const float4*)&Whh_s[cb * WPITCH + kbase + kk];
                float4 w1 = *(const float4*)&Whh_s[(cb + 16) * WPITCH + kbase + kk];
                float wa0[4] = {w0.x, w0.y, w0.z, w0.w};
                float wa1[4] = {w1.x, w1.y, w1.z, w1.w};
#pragma unroll
                for (int q2 = 0; q2 < 4; q2++) {
                    ull hp0 = *(const ull*)&hs[(kk + q2) * 64 + rb * 4];
                    ull hp1 = *(const ull*)&hs[(kk + q2) * 64 + rb * 4 + 2];
                    ull d0 = dup2f(wa0[q2]);
                    ull d1 = dup2f(wa1[q2]);
                    ffma2(acc00, hp0, d0);
                    ffma2(acc10, hp1, d0);
                    ffma2(acc01, hp0, d1);
                    ffma2(acc11, hp1, d1);
                }
            }
            if (ch < 7) {
                float* hnx = (ch & 1) ? hb0 : hb1;
                __syncthreads();   // all readers of hnx (chunk ch-1) are done; also orders hs reads
#pragma unroll
                for (int q = 0; q < 8; q++)
                    *(float4*)&hnx[q * 1024 + tid * 4] = r[q];
                __syncthreads();
            }
        }
        __syncthreads();   // chunk-7 compute done before zs (=hb0) overwrite

        // write z to smem [64][33]
        {
            float2 p;
            p = u2f(acc00); zs[(rb * 4 + 0) * 33 + cb] = p.x; zs[(rb * 4 + 1) * 33 + cb] = p.y;
            p = u2f(acc10); zs[(rb * 4 + 2) * 33 + cb] = p.x; zs[(rb * 4 + 3) * 33 + cb] = p.y;
            p = u2f(acc01); zs[(rb * 4 + 0) * 33 + cb + 16] = p.x; zs[(rb * 4 + 1) * 33 + cb + 16] = p.y;
            p = u2f(acc11); zs[(rb * 4 + 2) * 33 + cb + 16] = p.x; zs[(rb * 4 + 3) * 33 + cb + 16] = p.y;
        }
        __syncthreads();

        // gates: elements (b0, jl0) and (b0, jl0+4)
#pragma unroll
        for (int pe = 0; pe < 2; pe++) {
            int jl = jl0 + pe * 4;
            float zi = zs[b0 * 33 + jl];
            float zf = zs[b0 * 33 + 8 + jl];
            float zg = zs[b0 * 33 + 16 + jl];
            float zo = zs[b0 * 33 + 24 + jl];
            const float* Gp = g_G + ((size_t)t * BB + b0) * G4 + jb0 + jl;
            float pi = zi + Gp[0];
            float pf = zf + Gp[HH];
            float pg = zg + Gp[2 * HH];
            float po = zo + Gp[3 * HH];
            float iv = 1.f / (1.f + expf(-pi));
            float fv = 1.f / (1.f + expf(-pf));
            float ov = 1.f / (1.f + expf(-po));
            float gv = tanhf(pg);
            float cs = pe ? cst1 : cst0;
            cs = fv * cs + iv * gv;
            if (pe) cst1 = cs; else cst0 = cs;
            float h = ov * tanhf(cs);
            hdst[(jb0 + jl) * 64 + b0] = h;
            g_hseq[((size_t)b0 * TT + t) * HH + jb0 + jl] = h;
        }

        gsync((unsigned)(t + 1) * NCTA);
    }
}

// ---------------------------------------------------------------------------
// Output head: res[m] = sum_c (stu[m,c]-nkc)*nkc*W_out[c] + b_out. One warp/row.
// ---------------------------------------------------------------------------
__global__ void out_kernel(const float* __restrict__ Wout,
                           const float* __restrict__ bout,
                           float* __restrict__ dout) {
    int gw = (blockIdx.x * blockDim.x + threadIdx.x) >> 5;
    int lane = threadIdx.x & 31;
    if (gw >= MROWS) return;
    const float* stu = dout + MROWS + (size_t)gw * CN;
    float s = 0.f;
#pragma unroll
    for (int c = lane; c < CN; c += 32) {
        float nk = g_nextkc[gw * CN + c];
        s += (stu[c] - nk) * nk * Wout[c];
    }
#pragma unroll
    for (int o = 16; o; o >>= 1) s += __shfl_down_sync(0xffffffffu, s, o);
    if (lane == 0) dout[gw] = s + bout[0];
}

extern "C" void kernel_launch(void* const* d_in, const int* in_sizes, int n_in,
                              void* d_out, int out_size) {
    int wi = (n_in >= 14) ? 4 : 3;
    const float* q_hot   = (const float*)d_in[0];
    const int*   result  = (const int*)  d_in[1];
    const float* next_q  = (const float*)d_in[2];
    const float* W_kc    = (const float*)d_in[wi + 0];
    const float* b_kc    = (const float*)d_in[wi + 1];
    const float* W_ih    = (const float*)d_in[wi + 2];
    const float* W_hh    = (const float*)d_in[wi + 3];
    const float* b_ih    = (const float*)d_in[wi + 4];
    const float* b_hh    = (const float*)d_in[wi + 5];
    const float* W_state = (const float*)d_in[wi + 6];
    const float* b_state = (const float*)d_in[wi + 7];
    const float* W_out   = (const float*)d_in[wi + 8];
    const float* b_out   = (const float*)d_in[wi + 9];
    float* out = (float*)d_out;

    static int smem_set = 0;
    if (!smem_set) {
        cudaFuncSetAttribute(lstm_persist, cudaFuncAttributeMaxDynamicSharedMemorySize, SMEM_P);
        smem_set = 1;
    }

    init_misc<<<(HH * BB + 255) / 256, 256>>>();

    dim3 gk(CN / 128, MROWS / 128);       // (2, 100)
    sgemm_big<<<gk, 256>>>(q_hot, W_kc, b_kc, nullptr, nullptr,
                           MROWS, CN, NS, 1, result);
    sgemm_big<<<gk, 256>>>(next_q, W_kc, b_kc, nullptr, nullptr,
                           MROWS, CN, NS, 0, nullptr);
    dim3 gg(G4 / 128, MROWS / 128);       // (32, 100)
    sgemm_big<<<gg, 256>>>(nullptr, W_ih, b_ih, b_hh, nullptr,
                           MROWS, G4, 2 * CN, 2, nullptr);

    lstm_persist<<<NCTA, 256, SMEM_P>>>(W_hh);

    sgemm_big<<<gk, 256>>>(nullptr, W_state, b_state, nullptr, out + MROWS,
                           MROWS, CN, HH, 3, nullptr);
    out_kernel<<<(MROWS * 32 + 255) / 256, 256>>>(W_out, b_out, out);
}

// round 3
// speedup vs baseline: 1.5163x; 1.1741x over previous
#include <cuda_runtime.h>
#include <cuda_bf16.h>
#include <math.h>

typedef unsigned long long ull;
typedef unsigned uint32;

// Problem dims
#define BB 64
#define TT 200
#define NS 1024
#define CN 256
#define HH 1024
#define G4 4096
#define MROWS (BB*TT)   // 12800

// Persistent-kernel config
#define NCTA 128
#define KC 128
#define WPITCH 1028
#define SMEM_P ((32*WPITCH + 2*KC*64) * 4)

// ---- scratch globals (allocation-free) ----
__device__ float g_G[(size_t)MROWS * G4];          // [t][b][4096]
__device__ float g_nextkc[MROWS * CN];
__device__ float g_hb[2][HH * BB];                 // h ping-pong, [j][b]
__device__ unsigned g_barc;

// bf16 split planes
__device__ __nv_bfloat16 g_qh[(size_t)MROWS * NS],  g_ql[(size_t)MROWS * NS];
__device__ __nv_bfloat16 g_nqh[(size_t)MROWS * NS], g_nql[(size_t)MROWS * NS];
__device__ __nv_bfloat16 g_kcvh[(size_t)MROWS * 2 * CN], g_kcvl[(size_t)MROWS * 2 * CN];
__device__ __nv_bfloat16 g_hsh[(size_t)MROWS * HH], g_hsl[(size_t)MROWS * HH];
__device__ __nv_bfloat16 g_wkh[CN * NS],  g_wkl[CN * NS];
__device__ __nv_bfloat16 g_wih[G4 * 2 * CN], g_wil[G4 * 2 * CN];
__device__ __nv_bfloat16 g_wsh[CN * HH],  g_wsl[CN * HH];

// ---- helpers ----
__device__ __forceinline__ ull dup2f(float x) {
    ull r; asm("mov.b64 %0, {%1, %1};" : "=l"(r) : "f"(x)); return r;
}
__device__ __forceinline__ void ffma2(ull& d, ull a, ull b) {
    asm("fma.rn.f32x2 %0, %1, %2, %0;" : "+l"(d) : "l"(a), "l"(b));
}
__device__ __forceinline__ float2 u2f(ull v) {
    float2 f; asm("mov.b64 {%0, %1}, %2;" : "=f"(f.x), "=f"(f.y) : "l"(v)); return f;
}
__device__ __forceinline__ void splitbf(float v, __nv_bfloat16& h, __nv_bfloat16& l) {
    h = __float2bfloat16_rn(v);
    l = __float2bfloat16_rn(v - __bfloat162float(h));
}
__device__ __forceinline__ uint32 smaddr(const void* p) {
    return (uint32)__cvta_generic_to_shared(p);
}
__device__ __forceinline__ void ldm4(uint32* r, uint32 addr) {
    asm volatile("ldmatrix.sync.aligned.m8n8.x4.shared.b16 {%0,%1,%2,%3}, [%4];"
                 : "=r"(r[0]), "=r"(r[1]), "=r"(r[2]), "=r"(r[3]) : "r"(addr));
}
__device__ __forceinline__ void mma16816(float* c, const uint32* a, const uint32* b) {
    asm volatile("mma.sync.aligned.m16n8k16.row.col.f32.bf16.bf16.f32 "
                 "{%0,%1,%2,%3},{%4,%5,%6,%7},{%8,%9},{%0,%1,%2,%3};"
                 : "+f"(c[0]), "+f"(c[1]), "+f"(c[2]), "+f"(c[3])
                 : "r"(a[0]), "r"(a[1]), "r"(a[2]), "r"(a[3]), "r"(b[0]), "r"(b[1]));
}

__global__ void init_misc() {
    int i = blockIdx.x * blockDim.x + threadIdx.x;
    if (i < HH * BB) g_hb[0][i] = 0.f;
    if (i == 0) g_barc = 0u;
}

// fp32 -> (hi, lo) bf16 planes
__global__ void cvt_split(const float* __restrict__ src,
                          __nv_bfloat16* __restrict__ hi,
                          __nv_bfloat16* __restrict__ lo, int n4) {
    int i = blockIdx.x * blockDim.x + threadIdx.x;
    if (i >= n4) return;
    float4 v = ((const float4*)src)[i];
    __nv_bfloat16 h, l;
    splitbf(v.x, h, l); hi[4*i+0] = h; lo[4*i+0] = l;
    splitbf(v.y, h, l); hi[4*i+1] = h; lo[4*i+1] = l;
    splitbf(v.z, h, l); hi[4*i+2] = h; lo[4*i+2] = l;
    splitbf(v.w, h, l); hi[4*i+3] = h; lo[4*i+3] = l;
}

// ---------------------------------------------------------------------------
// bf16-split tensor-core GEMM: C[M,N] = A[M,K] @ B[N,K]^T + bias (+bias2)
// A,B given as hi/lo bf16 planes; C ≈ Ah·Bh + Ah·Bl + Al·Bh (fp32 accum).
// Tile 128x128x32, 256 threads (8 warps: 4m x 2n), warp tile 32x64.
// mode 0: C -> g_nextkc; 1: masked kc_vec -> g_kcvh/l planes;
// mode 2: A=g_kcv planes -> g_G[t][b][n]; 3: A=g_hs planes -> Cext fp32.
// ---------------------------------------------------------------------------
__global__ __launch_bounds__(256, 1) void mma_gemm(
        const __nv_bfloat16* __restrict__ Ah_, const __nv_bfloat16* __restrict__ Al_,
        const __nv_bfloat16* __restrict__ Bh,  const __nv_bfloat16* __restrict__ Bl,
        const float* __restrict__ bias, const float* __restrict__ bias2,
        float* __restrict__ Cext, int M, int N, int K, int mode,
        const int* __restrict__ resm) {
    __shared__ __nv_bfloat16 sAh[128][40], sAl[128][40];
    __shared__ __nv_bfloat16 sBh[128][40], sBl[128][40];

    const __nv_bfloat16* Ah = Ah_;
    const __nv_bfloat16* Al = Al_;
    if (mode == 2)      { Ah = g_kcvh; Al = g_kcvl; }
    else if (mode == 3) { Ah = g_hsh;  Al = g_hsl; }

    const int tid = threadIdx.x;
    const int m0 = blockIdx.y * 128, n0 = blockIdx.x * 128;
    const int warp = tid >> 5, lane = tid & 31;
    const int wm = warp >> 1, wn = warp & 1;

    const int lrow = tid >> 1;
    const int lcol = (tid & 1) * 16;

    float acc[2][8][4];
#pragma unroll
    for (int i = 0; i < 2; i++)
#pragma unroll
        for (int j = 0; j < 8; j++)
#pragma unroll
            for (int q = 0; q < 4; q++) acc[i][j][q] = 0.f;

    for (int k0 = 0; k0 < K; k0 += 32) {
        uint4 ah0 = *(const uint4*)&Ah[(size_t)(m0 + lrow) * K + k0 + lcol];
        uint4 ah1 = *(const uint4*)&Ah[(size_t)(m0 + lrow) * K + k0 + lcol + 8];
        uint4 al0 = *(const uint4*)&Al[(size_t)(m0 + lrow) * K + k0 + lcol];
        uint4 al1 = *(const uint4*)&Al[(size_t)(m0 + lrow) * K + k0 + lcol + 8];
        uint4 bh0 = *(const uint4*)&Bh[(size_t)(n0 + lrow) * K + k0 + lcol];
        uint4 bh1 = *(const uint4*)&Bh[(size_t)(n0 + lrow) * K + k0 + lcol + 8];
        uint4 bl0 = *(const uint4*)&Bl[(size_t)(n0 + lrow) * K + k0 + lcol];
        uint4 bl1 = *(const uint4*)&Bl[(size_t)(n0 + lrow) * K + k0 + lcol + 8];
        __syncthreads();
        *(uint4*)&sAh[lrow][lcol] = ah0; *(uint4*)&sAh[lrow][lcol + 8] = ah1;
        *(uint4*)&sAl[lrow][lcol] = al0; *(uint4*)&sAl[lrow][lcol + 8] = al1;
        *(uint4*)&sBh[lrow][lcol] = bh0; *(uint4*)&sBh[lrow][lcol + 8] = bh1;
        *(uint4*)&sBl[lrow][lcol] = bl0; *(uint4*)&sBl[lrow][lcol + 8] = bl1;
        __syncthreads();

#pragma unroll
        for (int ks = 0; ks < 32; ks += 16) {
            uint32 aH[2][4], aL[2][4];
#pragma unroll
            for (int mt = 0; mt < 2; mt++) {
                int row = wm * 32 + mt * 16 + (lane & 15);
                int col = ks + (lane >> 4) * 8;
                ldm4(aH[mt], smaddr(&sAh[row][col]));
                ldm4(aL[mt], smaddr(&sAl[row][col]));
            }
            uint32 bH[8][2], bL[8][2];
#pragma unroll
            for (int np = 0; np < 4; np++) {
                int row = wn * 64 + np * 16 + (lane & 7) + ((lane >> 4) & 1) * 8;
                int col = ks + ((lane >> 3) & 1) * 8;
                uint32 t4[4];
                ldm4(t4, smaddr(&sBh[row][col]));
                bH[2*np][0] = t4[0]; bH[2*np][1] = t4[1];
                bH[2*np+1][0] = t4[2]; bH[2*np+1][1] = t4[3];
                ldm4(t4, smaddr(&sBl[row][col]));
                bL[2*np][0] = t4[0]; bL[2*np][1] = t4[1];
                bL[2*np+1][0] = t4[2]; bL[2*np+1][1] = t4[3];
            }
#pragma unroll
            for (int mt = 0; mt < 2; mt++)
#pragma unroll
                for (int nt = 0; nt < 8; nt++) {
                    mma16816(acc[mt][nt], aH[mt], bH[nt]);
                    mma16816(acc[mt][nt], aH[mt], bL[nt]);
                    mma16816(acc[mt][nt], aL[mt], bH[nt]);
                }
        }
    }

    // epilogue
#pragma unroll
    for (int mt = 0; mt < 2; mt++) {
#pragma unroll
        for (int nt = 0; nt < 8; nt++) {
#pragma unroll
            for (int q = 0; q < 4; q++) {
                int m = m0 + wm * 32 + mt * 16 + (lane >> 2) + (q >> 1) * 8;
                int n = n0 + wn * 64 + nt * 8 + 2 * (lane & 3) + (q & 1);
                float v = acc[mt][nt][q] + bias[n];
                if (bias2) v += bias2[n];
                if (mode == 0) {
                    g_nextkc[m * CN + n] = v;
                } else if (mode == 1) {
                    float msk = (resm[m] == 1) ? 1.f : 0.f;
                    __nv_bfloat16 h, l;
                    splitbf(v * msk, h, l);
                    g_kcvh[(size_t)m * 2 * CN + n] = h;
                    g_kcvl[(size_t)m * 2 * CN + n] = l;
                    splitbf(v * (1.f - msk), h, l);
                    g_kcvh[(size_t)m * 2 * CN + CN + n] = h;
                    g_kcvl[(size_t)m * 2 * CN + CN + n] = l;
                } else if (mode == 2) {
                    int b = m / TT, t = m - b * TT;
                    g_G[((size_t)t * BB + b) * G4 + n] = v;
                } else {
                    Cext[(size_t)m * CN + n] = v;
                }
            }
        }
    }
}

// ---------------------------------------------------------------------------
// Persistent fused LSTM (as R2) + cheap barrier + G prefetch + bf16 hseq out.
// ---------------------------------------------------------------------------
__device__ __forceinline__ void gsync(unsigned target) {
    __syncthreads();
    if (threadIdx.x == 0) {
        __threadfence();
        atomicAdd(&g_barc, 1u);
        unsigned v;
        do {
            asm volatile("ld.acquire.gpu.global.u32 %0, [%1];" : "=r"(v) : "l"(&g_barc));
        } while (v < target);
    }
    __syncthreads();
}

__global__ __launch_bounds__(256, 1) void lstm_persist(const float* __restrict__ Whh) {
    extern __shared__ float sm[];
    float* Whh_s = sm;                        // [32][WPITCH]
    float* hb0 = sm + 32 * WPITCH;            // [KC][64]
    float* hb1 = hb0 + KC * 64;
    float* zs = hb0;                          // reuse: [64][33]

    const int tid = threadIdx.x;
    const int jb0 = blockIdx.x * 8;

    for (int idx = tid * 4; idx < 32 * 1024; idx += 256 * 4) {
        int c = idx >> 10, k = idx & 1023;
        int gr = ((c >> 3) << 10) + jb0 + (c & 7);
        *(float4*)&Whh_s[c * WPITCH + k] = *(const float4*)&Whh[(size_t)gr * HH + k];
    }
    __syncthreads();

    const int rb = tid >> 4;
    const int cb = tid & 15;
    const int b0 = tid & 63;
    const int jl0 = tid >> 6;

    float cst0 = 0.f, cst1 = 0.f;

    for (int t = 0; t < TT; t++) {
        const float* hsrc = g_hb[t & 1];
        float* hdst = g_hb[(t + 1) & 1];
        ull acc00 = 0, acc01 = 0, acc10 = 0, acc11 = 0;

        // prefetch gate biases for this step (consumed after z compute)
        const float* Gp = g_G + ((size_t)t * BB + b0) * G4 + jb0 + jl0;
        float gpi0 = Gp[0],      gpf0 = Gp[HH],     gpg0 = Gp[2*HH],     gpo0 = Gp[3*HH];
        float gpi1 = Gp[4],      gpf1 = Gp[HH+4],   gpg1 = Gp[2*HH+4],   gpo1 = Gp[3*HH+4];

        float4 r[8];
#pragma unroll
        for (int q = 0; q < 8; q++)
            r[q] = __ldcg((const float4*)&hsrc[q * 1024 + tid * 4]);
        __syncthreads();
#pragma unroll
        for (int q = 0; q < 8; q++)
            *(float4*)&hb0[q * 1024 + tid * 4] = r[q];
        __syncthreads();

        for (int ch = 0; ch < 8; ch++) {
            const float* hs = (ch & 1) ? hb1 : hb0;
            if (ch < 7) {
#pragma unroll
                for (int q = 0; q < 8; q++)
                    r[q] = __ldcg((const float4*)&hsrc[(ch + 1) * 8192 + q * 1024 + tid * 4]);
            }
            const int kbase = ch * KC;
#pragma unroll 4
            for (int kk = 0; kk < KC; kk += 4) {
                float4 w0 = *(const float4*)&Whh_s[cb * WPITCH + kbase + kk];
                float4 w1 = *(const float4*)&Whh_s[(cb + 16) * WPITCH + kbase + kk];
                float wa0[4] = {w0.x, w0.y, w0.z, w0.w};
                float wa1[4] = {w1.x, w1.y, w1.z, w1.w};
#pragma unroll
                for (int q2 = 0; q2 < 4; q2++) {
                    ull hp0 = *(const ull*)&hs[(kk + q2) * 64 + rb * 4];
                    ull hp1 = *(const ull*)&hs[(kk + q2) * 64 + rb * 4 + 2];
                    ull d0 = dup2f(wa0[q2]);
                    ull d1 = dup2f(wa1[q2]);
                    ffma2(acc00, hp0, d0);
                    ffma2(acc10, hp1, d0);
                    ffma2(acc01, hp0, d1);
                    ffma2(acc11, hp1, d1);
                }
            }
            if (ch < 7) {
                float* hnx = (ch & 1) ? hb0 : hb1;
                __syncthreads();
#pragma unroll
                for (int q = 0; q < 8; q++)
                    *(float4*)&hnx[q * 1024 + tid * 4] = r[q];
                __syncthreads();
            }
        }
        __syncthreads();

        {
            float2 p;
            p = u2f(acc00); zs[(rb * 4 + 0) * 33 + cb] = p.x; zs[(rb * 4 + 1) * 33 + cb] = p.y;
            p = u2f(acc10); zs[(rb * 4 + 2) * 33 + cb] = p.x; zs[(rb * 4 + 3) * 33 + cb] = p.y;
            p = u2f(acc01); zs[(rb * 4 + 0) * 33 + cb + 16] = p.x; zs[(rb * 4 + 1) * 33 + cb + 16] = p.y;
            p = u2f(acc11); zs[(rb * 4 + 2) * 33 + cb + 16] = p.x; zs[(rb * 4 + 3) * 33 + cb + 16] = p.y;
        }
        __syncthreads();

#pragma unroll
        for (int pe = 0; pe < 2; pe++) {
            int jl = jl0 + pe * 4;
            float pi = zs[b0 * 33 + jl]       + (pe ? gpi1 : gpi0);
            float pf = zs[b0 * 33 + 8 + jl]   + (pe ? gpf1 : gpf0);
            float pg = zs[b0 * 33 + 16 + jl]  + (pe ? gpg1 : gpg0);
            float po = zs[b0 * 33 + 24 + jl]  + (pe ? gpo1 : gpo0);
            float iv = 1.f / (1.f + expf(-pi));
            float fv = 1.f / (1.f + expf(-pf));
            float ov = 1.f / (1.f + expf(-po));
            float gv = tanhf(pg);
            float cs = pe ? cst1 : cst0;
            cs = fv * cs + iv * gv;
            if (pe) cst1 = cs; else cst0 = cs;
            float h = ov * tanhf(cs);
            hdst[(jb0 + jl) * 64 + b0] = h;
            __nv_bfloat16 hh, hl;
            splitbf(h, hh, hl);
            size_t hidx = ((size_t)b0 * TT + t) * HH + jb0 + jl;
            g_hsh[hidx] = hh;
            g_hsl[hidx] = hl;
        }

        gsync((unsigned)(t + 1) * NCTA);
    }
}

// ---------------------------------------------------------------------------
__global__ void out_kernel(const float* __restrict__ Wout,
                           const float* __restrict__ bout,
                           float* __restrict__ dout) {
    int gw = (blockIdx.x * blockDim.x + threadIdx.x) >> 5;
    int lane = threadIdx.x & 31;
    if (gw >= MROWS) return;
    const float* stu = dout + MROWS + (size_t)gw * CN;
    float s = 0.f;
#pragma unroll
    for (int c = lane; c < CN; c += 32) {
        float nk = g_nextkc[gw * CN + c];
        s += (stu[c] - nk) * nk * Wout[c];
    }
#pragma unroll
    for (int o = 16; o; o >>= 1) s += __shfl_down_sync(0xffffffffu, s, o);
    if (lane == 0) dout[gw] = s + bout[0];
}

extern "C" void kernel_launch(void* const* d_in, const int* in_sizes, int n_in,
                              void* d_out, int out_size) {
    int wi = (n_in >= 14) ? 4 : 3;
    const float* q_hot   = (const float*)d_in[0];
    const int*   result  = (const int*)  d_in[1];
    const float* next_q  = (const float*)d_in[2];
    const float* W_kc    = (const float*)d_in[wi + 0];
    const float* b_kc    = (const float*)d_in[wi + 1];
    const float* W_ih    = (const float*)d_in[wi + 2];
    const float* W_hh    = (const float*)d_in[wi + 3];
    const float* b_ih    = (const float*)d_in[wi + 4];
    const float* b_hh    = (const float*)d_in[wi + 5];
    const float* W_state = (const float*)d_in[wi + 6];
    const float* b_state = (const float*)d_in[wi + 7];
    const float* W_out   = (const float*)d_in[wi + 8];
    const float* b_out   = (const float*)d_in[wi + 9];
    float* out = (float*)d_out;

    static int smem_set = 0;
    if (!smem_set) {
        cudaFuncSetAttribute(lstm_persist, cudaFuncAttributeMaxDynamicSharedMemorySize, SMEM_P);
        smem_set = 1;
    }

    init_misc<<<(HH * BB + 255) / 256, 256>>>();

    // pointers to split planes (device symbols usable directly in kernels;
    // for cvt we pass via small launcher kernels' symbol addresses)
    // cvt: inputs + weights
    {
        __nv_bfloat16 *qh, *ql, *nqh, *nql, *wkh, *wkl, *wih, *wil, *wsh, *wsl;
        cudaGetSymbolAddress((void**)&qh,  g_qh);  cudaGetSymbolAddress((void**)&ql,  g_ql);
        cudaGetSymbolAddress((void**)&nqh, g_nqh); cudaGetSymbolAddress((void**)&nql, g_nql);
        cudaGetSymbolAddress((void**)&wkh, g_wkh); cudaGetSymbolAddress((void**)&wkl, g_wkl);
        cudaGetSymbolAddress((void**)&wih, g_wih); cudaGetSymbolAddress((void**)&wil, g_wil);
        cudaGetSymbolAddress((void**)&wsh, g_wsh); cudaGetSymbolAddress((void**)&wsl, g_wsl);

        int n4q = MROWS * NS / 4;
        cvt_split<<<(n4q + 255) / 256, 256>>>(q_hot, qh, ql, n4q);
        cvt_split<<<(n4q + 255) / 256, 256>>>(next_q, nqh, nql, n4q);
        int n4k = CN * NS / 4;
        cvt_split<<<(n4k + 255) / 256, 256>>>(W_kc, wkh, wkl, n4k);
        int n4i = G4 * 2 * CN / 4;
        cvt_split<<<(n4i + 255) / 256, 256>>>(W_ih, wih, wil, n4i);
        int n4s = CN * HH / 4;
        cvt_split<<<(n4s + 255) / 256, 256>>>(W_state, wsh, wsl, n4s);

        dim3 gk(CN / 128, MROWS / 128);       // (2, 100)
        // kc_hot -> masked kc_vec bf16 planes (mode 1)
        mma_gemm<<<gk, 256>>>(qh, ql, wkh, wkl, b_kc, nullptr, nullptr,
                              MROWS, CN, NS, 1, result);
        // next_kc_hot fp32 (mode 0)
        mma_gemm<<<gk, 256>>>(nqh, nql, wkh, wkl, b_kc, nullptr, nullptr,
                              MROWS, CN, NS, 0, nullptr);
        // gx (mode 2)
        dim3 gg(G4 / 128, MROWS / 128);       // (32, 100)
        mma_gemm<<<gg, 256>>>(nullptr, nullptr, wih, wil, b_ih, b_hh, nullptr,
                              MROWS, G4, 2 * CN, 2, nullptr);

        lstm_persist<<<NCTA, 256, SMEM_P>>>(W_hh);

        // stu_state (mode 3)
        mma_gemm<<<gk, 256>>>(nullptr, nullptr, wsh, wsl, b_state, nullptr,
                              out + MROWS, MROWS, CN, HH, 3, nullptr);
        out_kernel<<<(MROWS * 32 + 255) / 256, 256>>>(W_out, b_out, out);
    }
}

// round 4
// speedup vs baseline: 2.7786x; 1.8325x over previous
#include <cuda_runtime.h>
#include <cuda_bf16.h>
#include <math.h>

typedef unsigned long long ull;
typedef unsigned uint32;

// Problem dims
#define BB 64
#define TT 200
#define NS 1024
#define CN 256
#define HH 1024
#define G4 4096
#define MROWS (BB*TT)   // 12800

// Persistent-kernel config
#define NCTA 128
#define WHP 1032        // Whh smem pitch (bf16)
#define SAP 136         // h-chunk smem pitch (bf16)

// smem offsets (bytes), all 16B aligned
#define OFF_WH   0
#define OFF_WL   (OFF_WH + 32*WHP*2)          // 66048
#define OFF_SA   (OFF_WL + 32*WHP*2)          // 132096: 2 bufs x 2 planes x 64*SAP bf16
#define SA_BUF   (2*64*SAP*2)                  // bytes per buffer (both planes) = 34816
#define OFF_ZS   (OFF_SA + 2*SA_BUF)          // 201728: 64*33 fp32
#define OFF_HGH  (OFF_ZS + 64*33*4)           // 210176: 64*8 bf16
#define OFF_HGL  (OFF_HGH + 64*8*2)           // 211200
#define SMEM_P   (OFF_HGL + 64*8*2)           // 212224

// ---- scratch globals (allocation-free) ----
__device__ float g_G[(size_t)MROWS * G4];          // [t][b][4096]
__device__ float g_nextkc[MROWS * CN];
__device__ __nv_bfloat16 g_ha[2][2][BB * HH];      // h ping-pong, [buf][plane][m*1024+k]
__device__ unsigned g_barc;

// bf16 split planes
__device__ __nv_bfloat16 g_qh[(size_t)MROWS * NS],  g_ql[(size_t)MROWS * NS];
__device__ __nv_bfloat16 g_nqh[(size_t)MROWS * NS], g_nql[(size_t)MROWS * NS];
__device__ __nv_bfloat16 g_kcvh[(size_t)MROWS * 2 * CN], g_kcvl[(size_t)MROWS * 2 * CN];
__device__ __nv_bfloat16 g_hsh[(size_t)MROWS * HH], g_hsl[(size_t)MROWS * HH];
__device__ __nv_bfloat16 g_wkh[CN * NS],  g_wkl[CN * NS];
__device__ __nv_bfloat16 g_wih[G4 * 2 * CN], g_wil[G4 * 2 * CN];
__device__ __nv_bfloat16 g_wsh[CN * HH],  g_wsl[CN * HH];

// ---- helpers ----
__device__ __forceinline__ void splitbf(float v, __nv_bfloat16& h, __nv_bfloat16& l) {
    h = __float2bfloat16_rn(v);
    l = __float2bfloat16_rn(v - __bfloat162float(h));
}
__device__ __forceinline__ uint32 smaddr(const void* p) {
    return (uint32)__cvta_generic_to_shared(p);
}
__device__ __forceinline__ void ldm4(uint32* r, uint32 addr) {
    asm volatile("ldmatrix.sync.aligned.m8n8.x4.shared.b16 {%0,%1,%2,%3}, [%4];"
                 : "=r"(r[0]), "=r"(r[1]), "=r"(r[2]), "=r"(r[3]) : "r"(addr));
}
__device__ __forceinline__ void mma16816(float* c, const uint32* a, const uint32* b) {
    asm volatile("mma.sync.aligned.m16n8k16.row.col.f32.bf16.bf16.f32 "
                 "{%0,%1,%2,%3},{%4,%5,%6,%7},{%8,%9},{%0,%1,%2,%3};"
                 : "+f"(c[0]), "+f"(c[1]), "+f"(c[2]), "+f"(c[3])
                 : "r"(a[0]), "r"(a[1]), "r"(a[2]), "r"(a[3]), "r"(b[0]), "r"(b[1]));
}

__global__ void init_misc() {
    int i = blockIdx.x * blockDim.x + threadIdx.x;
    // zero both planes of h buffer 0 (64*1024 bf16 each = 32768 uint32 each)
    if (i < 2 * BB * HH / 2) ((uint32*)g_ha[0])[i] = 0u;
    if (i == 0) g_barc = 0u;
}

// fp32 -> (hi, lo) bf16 planes
__global__ void cvt_split(const float* __restrict__ src,
                          __nv_bfloat16* __restrict__ hi,
                          __nv_bfloat16* __restrict__ lo, int n4) {
    int i = blockIdx.x * blockDim.x + threadIdx.x;
    if (i >= n4) return;
    float4 v = ((const float4*)src)[i];
    __nv_bfloat16 h, l;
    splitbf(v.x, h, l); hi[4*i+0] = h; lo[4*i+0] = l;
    splitbf(v.y, h, l); hi[4*i+1] = h; lo[4*i+1] = l;
    splitbf(v.z, h, l); hi[4*i+2] = h; lo[4*i+2] = l;
    splitbf(v.w, h, l); hi[4*i+3] = h; lo[4*i+3] = l;
}

// ---------------------------------------------------------------------------
// bf16-split tensor-core GEMM (unchanged from R3, validated)
// ---------------------------------------------------------------------------
__global__ __launch_bounds__(256, 1) void mma_gemm(
        const __nv_bfloat16* __restrict__ Ah_, const __nv_bfloat16* __restrict__ Al_,
        const __nv_bfloat16* __restrict__ Bh,  const __nv_bfloat16* __restrict__ Bl,
        const float* __restrict__ bias, const float* __restrict__ bias2,
        float* __restrict__ Cext, int M, int N, int K, int mode,
        const int* __restrict__ resm) {
    __shared__ __nv_bfloat16 sAh[128][40], sAl[128][40];
    __shared__ __nv_bfloat16 sBh[128][40], sBl[128][40];

    const __nv_bfloat16* Ah = Ah_;
    const __nv_bfloat16* Al = Al_;
    if (mode == 2)      { Ah = g_kcvh; Al = g_kcvl; }
    else if (mode == 3) { Ah = g_hsh;  Al = g_hsl; }

    const int tid = threadIdx.x;
    const int m0 = blockIdx.y * 128, n0 = blockIdx.x * 128;
    const int warp = tid >> 5, lane = tid & 31;
    const int wm = warp >> 1, wn = warp & 1;

    const int lrow = tid >> 1;
    const int lcol = (tid & 1) * 16;

    float acc[2][8][4];
#pragma unroll
    for (int i = 0; i < 2; i++)
#pragma unroll
        for (int j = 0; j < 8; j++)
#pragma unroll
            for (int q = 0; q < 4; q++) acc[i][j][q] = 0.f;

    for (int k0 = 0; k0 < K; k0 += 32) {
        uint4 ah0 = *(const uint4*)&Ah[(size_t)(m0 + lrow) * K + k0 + lcol];
        uint4 ah1 = *(const uint4*)&Ah[(size_t)(m0 + lrow) * K + k0 + lcol + 8];
        uint4 al0 = *(const uint4*)&Al[(size_t)(m0 + lrow) * K + k0 + lcol];
        uint4 al1 = *(const uint4*)&Al[(size_t)(m0 + lrow) * K + k0 + lcol + 8];
        uint4 bh0 = *(const uint4*)&Bh[(size_t)(n0 + lrow) * K + k0 + lcol];
        uint4 bh1 = *(const uint4*)&Bh[(size_t)(n0 + lrow) * K + k0 + lcol + 8];
        uint4 bl0 = *(const uint4*)&Bl[(size_t)(n0 + lrow) * K + k0 + lcol];
        uint4 bl1 = *(const uint4*)&Bl[(size_t)(n0 + lrow) * K + k0 + lcol + 8];
        __syncthreads();
        *(uint4*)&sAh[lrow][lcol] = ah0; *(uint4*)&sAh[lrow][lcol + 8] = ah1;
        *(uint4*)&sAl[lrow][lcol] = al0; *(uint4*)&sAl[lrow][lcol + 8] = al1;
        *(uint4*)&sBh[lrow][lcol] = bh0; *(uint4*)&sBh[lrow][lcol + 8] = bh1;
        *(uint4*)&sBl[lrow][lcol] = bl0; *(uint4*)&sBl[lrow][lcol + 8] = bl1;
        __syncthreads();

#pragma unroll
        for (int ks = 0; ks < 32; ks += 16) {
            uint32 aH[2][4], aL[2][4];
#pragma unroll
            for (int mt = 0; mt < 2; mt++) {
                int row = wm * 32 + mt * 16 + (lane & 15);
                int col = ks + (lane >> 4) * 8;
                ldm4(aH[mt], smaddr(&sAh[row][col]));
                ldm4(aL[mt], smaddr(&sAl[row][col]));
            }
            uint32 bH[8][2], bL[8][2];
#pragma unroll
            for (int np = 0; np < 4; np++) {
                int row = wn * 64 + np * 16 + (lane & 7) + ((lane >> 4) & 1) * 8;
                int col = ks + ((lane >> 3) & 1) * 8;
                uint32 t4[4];
                ldm4(t4, smaddr(&sBh[row][col]));
                bH[2*np][0] = t4[0]; bH[2*np][1] = t4[1];
                bH[2*np+1][0] = t4[2]; bH[2*np+1][1] = t4[3];
                ldm4(t4, smaddr(&sBl[row][col]));
                bL[2*np][0] = t4[0]; bL[2*np][1] = t4[1];
                bL[2*np+1][0] = t4[2]; bL[2*np+1][1] = t4[3];
            }
#pragma unroll
            for (int mt = 0; mt < 2; mt++)
#pragma unroll
                for (int nt = 0; nt < 8; nt++) {
                    mma16816(acc[mt][nt], aH[mt], bH[nt]);
                    mma16816(acc[mt][nt], aH[mt], bL[nt]);
                    mma16816(acc[mt][nt], aL[mt], bH[nt]);
                }
        }
    }

#pragma unroll
    for (int mt = 0; mt < 2; mt++) {
#pragma unroll
        for (int nt = 0; nt < 8; nt++) {
#pragma unroll
            for (int q = 0; q < 4; q++) {
                int m = m0 + wm * 32 + mt * 16 + (lane >> 2) + (q >> 1) * 8;
                int n = n0 + wn * 64 + nt * 8 + 2 * (lane & 3) + (q & 1);
                float v = acc[mt][nt][q] + bias[n];
                if (bias2) v += bias2[n];
                if (mode == 0) {
                    g_nextkc[m * CN + n] = v;
                } else if (mode == 1) {
                    float msk = (resm[m] == 1) ? 1.f : 0.f;
                    __nv_bfloat16 h, l;
                    splitbf(v * msk, h, l);
                    g_kcvh[(size_t)m * 2 * CN + n] = h;
                    g_kcvl[(size_t)m * 2 * CN + n] = l;
                    splitbf(v * (1.f - msk), h, l);
                    g_kcvh[(size_t)m * 2 * CN + CN + n] = h;
                    g_kcvl[(size_t)m * 2 * CN + CN + n] = l;
                } else if (mode == 2) {
                    int b = m / TT, t = m - b * TT;
                    g_G[((size_t)t * BB + b) * G4 + n] = v;
                } else {
                    Cext[(size_t)m * CN + n] = v;
                }
            }
        }
    }
}

// ---------------------------------------------------------------------------
// grid barrier (arrive atomic + acquire-load poll)
// ---------------------------------------------------------------------------
__device__ __forceinline__ void gsync(unsigned target) {
    __syncthreads();
    if (threadIdx.x == 0) {
        __threadfence();
        atomicAdd(&g_barc, 1u);
        unsigned v;
        do {
            asm volatile("ld.acquire.gpu.global.u32 %0, [%1];" : "=r"(v) : "l"(&g_barc));
        } while (v < target);
    }
    __syncthreads();
}

// ---------------------------------------------------------------------------
// Persistent fused LSTM with tensor-core recurrence.
// 128 CTAs; CTA k owns hidden units [8k, 8k+8) => 32 gate columns.
// Whh slice in SMEM as bf16 hi/lo; h in global bf16 hi/lo ping-pong planes.
// Per step: z = h @ Whh_slice^T via ldmatrix+mma (3-product bf16 split),
// gates in registers, h written as bf16 planes, grid barrier.
// ---------------------------------------------------------------------------
__global__ __launch_bounds__(256, 1) void lstm_persist(const float* __restrict__ Whh) {
    extern __shared__ char sm_raw[];
    __nv_bfloat16* whh_h = (__nv_bfloat16*)(sm_raw + OFF_WH);   // [32][WHP]
    __nv_bfloat16* whh_l = (__nv_bfloat16*)(sm_raw + OFF_WL);
    float* zs = (float*)(sm_raw + OFF_ZS);                       // [64][33]
    __nv_bfloat16* hgh = (__nv_bfloat16*)(sm_raw + OFF_HGH);     // [64][8]
    __nv_bfloat16* hgl = (__nv_bfloat16*)(sm_raw + OFF_HGL);

    const int tid = threadIdx.x;
    const int jb0 = blockIdx.x * 8;
    const int warp = tid >> 5, lane = tid & 31;
    const int wm = warp >> 1, wn = warp & 1;   // 4 x 2

    // Load + split W_hh slice: local col c=g*8+jl -> global row g*1024 + jb0 + jl
    for (int idx = tid; idx < 32 * 1024; idx += 256) {
        int c = idx >> 10, k = idx & 1023;
        int gr = ((c >> 3) << 10) + jb0 + (c & 7);
        float w = Whh[(size_t)gr * HH + k];
        __nv_bfloat16 h, l;
        splitbf(w, h, l);
        whh_h[c * WHP + k] = h;
        whh_l[c * WHP + k] = l;
    }
    __syncthreads();

    const int b0 = tid & 63;
    const int jl0 = tid >> 6;

    // staging copy indices: 4 passes x 256 threads cover 64 rows x 128 bf16 (one plane)
    const int srow[4] = { (0*256+tid) >> 4, (1*256+tid) >> 4, (2*256+tid) >> 4, (3*256+tid) >> 4 };
    const int scol = (tid & 15) * 8;   // bf16 col within chunk

    float cst0 = 0.f, cst1 = 0.f;

    for (int t = 0; t < TT; t++) {
        const __nv_bfloat16* hsH = g_ha[t & 1][0];
        const __nv_bfloat16* hsL = g_ha[t & 1][1];
        const int nb = (t + 1) & 1;

        // prefetch gate biases
        const float* Gp = g_G + ((size_t)t * BB + b0) * G4 + jb0 + jl0;
        float gpi0 = Gp[0], gpf0 = Gp[HH], gpg0 = Gp[2*HH], gpo0 = Gp[3*HH];
        float gpi1 = Gp[4], gpf1 = Gp[HH+4], gpg1 = Gp[2*HH+4], gpo1 = Gp[3*HH+4];

        float acc0[4] = {0.f, 0.f, 0.f, 0.f};
        float acc1[4] = {0.f, 0.f, 0.f, 0.f};

        // preload chunk 0
        uint4 rh[4], rl[4];
#pragma unroll
        for (int p = 0; p < 4; p++) {
            rh[p] = __ldcg((const uint4*)&hsH[srow[p] * HH + scol]);
            rl[p] = __ldcg((const uint4*)&hsL[srow[p] * HH + scol]);
        }
        {
            __nv_bfloat16* dAh = (__nv_bfloat16*)(sm_raw + OFF_SA);
            __nv_bfloat16* dAl = dAh + 64 * SAP;
#pragma unroll
            for (int p = 0; p < 4; p++) {
                *(uint4*)&dAh[srow[p] * SAP + scol] = rh[p];
                *(uint4*)&dAl[srow[p] * SAP + scol] = rl[p];
            }
        }
        __syncthreads();

        for (int ch = 0; ch < 8; ch++) {
            const __nv_bfloat16* sAh = (const __nv_bfloat16*)(sm_raw + OFF_SA + (ch & 1) * SA_BUF);
            const __nv_bfloat16* sAl = sAh + 64 * SAP;

            if (ch < 7) {
#pragma unroll
                for (int p = 0; p < 4; p++) {
                    rh[p] = __ldcg((const uint4*)&hsH[srow[p] * HH + (ch + 1) * 128 + scol]);
                    rl[p] = __ldcg((const uint4*)&hsL[srow[p] * HH + (ch + 1) * 128 + scol]);
                }
            }

            // 8 k-steps of k16
            const int arow = wm * 16 + (lane & 15);
            const int acol = (lane >> 4) * 8;
            const int brow = wn * 16 + (lane & 7) + ((lane >> 4) & 1) * 8;
            const int bcol = ch * 128 + ((lane >> 3) & 1) * 8;
#pragma unroll
            for (int ks = 0; ks < 128; ks += 16) {
                uint32 aH[4], aL[4], t4[4];
                ldm4(aH, smaddr(&sAh[arow * SAP + ks + acol]));
                ldm4(aL, smaddr(&sAl[arow * SAP + ks + acol]));
                ldm4(t4, smaddr(&whh_h[brow * WHP + bcol + ks]));
                uint32 bH0[2] = {t4[0], t4[1]}, bH1[2] = {t4[2], t4[3]};
                ldm4(t4, smaddr(&whh_l[brow * WHP + bcol + ks]));
                uint32 bL0[2] = {t4[0], t4[1]}, bL1[2] = {t4[2], t4[3]};
                mma16816(acc0, aH, bH0);
                mma16816(acc1, aH, bH1);
                mma16816(acc0, aH, bL0);
                mma16816(acc1, aH, bL1);
                mma16816(acc0, aL, bH0);
                mma16816(acc1, aL, bH1);
            }

            if (ch < 7) {
                __nv_bfloat16* dAh = (__nv_bfloat16*)(sm_raw + OFF_SA + ((ch + 1) & 1) * SA_BUF);
                __nv_bfloat16* dAl = dAh + 64 * SAP;
                // prior readers of this buffer finished at the sync ending iter ch-1;
                // current-iter ldmatrix reads (other buffer) must finish before its
                // overwrite next iter -> sync below covers both.
#pragma unroll
                for (int p = 0; p < 4; p++) {
                    *(uint4*)&dAh[srow[p] * SAP + scol] = rh[p];
                    *(uint4*)&dAl[srow[p] * SAP + scol] = rl[p];
                }
                __syncthreads();
            }
        }

        // epilogue: C frags -> zs[64][33]
        {
            int mrow = wm * 16 + (lane >> 2);
            int ncol = wn * 16 + 2 * (lane & 3);
#pragma unroll
            for (int q = 0; q < 4; q++) {
                zs[(mrow + (q >> 1) * 8) * 33 + ncol + (q & 1)] = acc0[q];
                zs[(mrow + (q >> 1) * 8) * 33 + ncol + 8 + (q & 1)] = acc1[q];
            }
        }
        __syncthreads();

        // gates: elements (b0, jl0) and (b0, jl0+4)
#pragma unroll
        for (int pe = 0; pe < 2; pe++) {
            int jl = jl0 + pe * 4;
            float pi = zs[b0 * 33 + jl]      + (pe ? gpi1 : gpi0);
            float pf = zs[b0 * 33 + 8 + jl]  + (pe ? gpf1 : gpf0);
            float pg = zs[b0 * 33 + 16 + jl] + (pe ? gpg1 : gpg0);
            float po = zs[b0 * 33 + 24 + jl] + (pe ? gpo1 : gpo0);
            float iv = 1.f / (1.f + expf(-pi));
            float fv = 1.f / (1.f + expf(-pf));
            float ov = 1.f / (1.f + expf(-po));
            float gv = tanhf(pg);
            float cs = pe ? cst1 : cst0;
            cs = fv * cs + iv * gv;
            if (pe) cst1 = cs; else cst0 = cs;
            float h = ov * tanhf(cs);
            __nv_bfloat16 hh, hl;
            splitbf(h, hh, hl);
            hgh[b0 * 8 + jl] = hh;
            hgl[b0 * 8 + jl] = hl;
        }
        __syncthreads();

        // vectorized 16B stores of h rows
        {
            int r = tid & 63;
            if (tid < 64) {
                *(uint4*)&g_ha[nb][0][r * HH + jb0] = *(const uint4*)&hgh[r * 8];
            } else if (tid < 128) {
                *(uint4*)&g_ha[nb][1][r * HH + jb0] = *(const uint4*)&hgl[r * 8];
            } else if (tid < 192) {
                *(uint4*)&g_hsh[((size_t)r * TT + t) * HH + jb0] = *(const uint4*)&hgh[r * 8];
            } else {
                *(uint4*)&g_hsl[((size_t)r * TT + t) * HH + jb0] = *(const uint4*)&hgl[r * 8];
            }
        }

        gsync((unsigned)(t + 1) * NCTA);
    }
}

// ---------------------------------------------------------------------------
__global__ void out_kernel(const float* __restrict__ Wout,
                           const float* __restrict__ bout,
                           float* __restrict__ dout) {
    int gw = (blockIdx.x * blockDim.x + threadIdx.x) >> 5;
    int lane = threadIdx.x & 31;
    if (gw >= MROWS) return;
    const float* stu = dout + MROWS + (size_t)gw * CN;
    float s = 0.f;
#pragma unroll
    for (int c = lane; c < CN; c += 32) {
        float nk = g_nextkc[gw * CN + c];
        s += (stu[c] - nk) * nk * Wout[c];
    }
#pragma unroll
    for (int o = 16; o; o >>= 1) s += __shfl_down_sync(0xffffffffu, s, o);
    if (lane == 0) dout[gw] = s + bout[0];
}

extern "C" void kernel_launch(void* const* d_in, const int* in_sizes, int n_in,
                              void* d_out, int out_size) {
    int wi = (n_in >= 14) ? 4 : 3;
    const float* q_hot   = (const float*)d_in[0];
    const int*   result  = (const int*)  d_in[1];
    const float* next_q  = (const float*)d_in[2];
    const float* W_kc    = (const float*)d_in[wi + 0];
    const float* b_kc    = (const float*)d_in[wi + 1];
    const float* W_ih    = (const float*)d_in[wi + 2];
    const float* W_hh    = (const float*)d_in[wi + 3];
    const float* b_ih    = (const float*)d_in[wi + 4];
    const float* b_hh    = (const float*)d_in[wi + 5];
    const float* W_state = (const float*)d_in[wi + 6];
    const float* b_state = (const float*)d_in[wi + 7];
    const float* W_out   = (const float*)d_in[wi + 8];
    const float* b_out   = (const float*)d_in[wi + 9];
    float* out = (float*)d_out;

    static int smem_set = 0;
    if (!smem_set) {
        cudaFuncSetAttribute(lstm_persist, cudaFuncAttributeMaxDynamicSharedMemorySize, SMEM_P);
        smem_set = 1;
    }

    init_misc<<<(2 * BB * HH / 2 + 255) / 256, 256>>>();

    __nv_bfloat16 *qh, *ql, *nqh, *nql, *wkh, *wkl, *wih, *wil, *wsh, *wsl;
    cudaGetSymbolAddress((void**)&qh,  g_qh);  cudaGetSymbolAddress((void**)&ql,  g_ql);
    cudaGetSymbolAddress((void**)&nqh, g_nqh); cudaGetSymbolAddress((void**)&nql, g_nql);
    cudaGetSymbolAddress((void**)&wkh, g_wkh); cudaGetSymbolAddress((void**)&wkl, g_wkl);
    cudaGetSymbolAddress((void**)&wih, g_wih); cudaGetSymbolAddress((void**)&wil, g_wil);
    cudaGetSymbolAddress((void**)&wsh, g_wsh); cudaGetSymbolAddress((void**)&wsl, g_wsl);

    int n4q = MROWS * NS / 4;
    cvt_split<<<(n4q + 255) / 256, 256>>>(q_hot, qh, ql, n4q);
    cvt_split<<<(n4q + 255) / 256, 256>>>(next_q, nqh, nql, n4q);
    int n4k = CN * NS / 4;
    cvt_split<<<(n4k + 255) / 256, 256>>>(W_kc, wkh, wkl, n4k);
    int n4i = G4 * 2 * CN / 4;
    cvt_split<<<(n4i + 255) / 256, 256>>>(W_ih, wih, wil, n4i);
    int n4s = CN * HH / 4;
    cvt_split<<<(n4s + 255) / 256, 256>>>(W_state, wsh, wsl, n4s);

    dim3 gk(CN / 128, MROWS / 128);       // (2, 100)
    mma_gemm<<<gk, 256>>>(qh, ql, wkh, wkl, b_kc, nullptr, nullptr,
                          MROWS, CN, NS, 1, result);
    mma_gemm<<<gk, 256>>>(nqh, nql, wkh, wkl, b_kc, nullptr, nullptr,
                          MROWS, CN, NS, 0, nullptr);
    dim3 gg(G4 / 128, MROWS / 128);       // (32, 100)
    mma_gemm<<<gg, 256>>>(nullptr, nullptr, wih, wil, b_ih, b_hh, nullptr,
                          MROWS, G4, 2 * CN, 2, nullptr);

    lstm_persist<<<NCTA, 256, SMEM_P>>>(W_hh);

    mma_gemm<<<gk, 256>>>(nullptr, nullptr, wsh, wsl, b_state, nullptr,
                          out + MROWS, MROWS, CN, HH, 3, nullptr);
    out_kernel<<<(MROWS * 32 + 255) / 256, 256>>>(W_out, b_out, out);
}

// round 8
// speedup vs baseline: 3.3652x; 1.2111x over previous
#include <cuda_runtime.h>
#include <cuda_bf16.h>
#include <math.h>

typedef unsigned long long ull;
typedef unsigned uint32;

// Problem dims
#define BB 64
#define TT 200
#define NS 1024
#define CN 256
#define HH 1024
#define G4 4096
#define MROWS (BB*TT)   // 12800

// Persistent-kernel config
#define NCTA 128
#define WHP 1032                 // Whh staging pitch (bf16)
#define PSTR 40                  // partial-sum row stride (floats)
#define SMEM_LSTM 132096         // max(whh staging 132096, partials 81920)
#define FRAGW 32768              // uint32 per plane per buffer (64 k16 * 4 m16 * 32 * 4)

// ---- scratch globals (allocation-free) ----
__device__ float g_G[(size_t)MROWS * G4];          // [t][b][4096]
__device__ float g_nextkc[MROWS * CN];
__device__ uint32 g_hfrag[2][2][FRAGW];            // h in A-fragment layout [buf][plane]
__device__ unsigned g_barc;

// bf16 split planes
__device__ __nv_bfloat16 g_qh[(size_t)MROWS * NS],  g_ql[(size_t)MROWS * NS];
__device__ __nv_bfloat16 g_nqh[(size_t)MROWS * NS], g_nql[(size_t)MROWS * NS];
__device__ __nv_bfloat16 g_kcvh[(size_t)MROWS * 2 * CN], g_kcvl[(size_t)MROWS * 2 * CN];
__device__ __nv_bfloat16 g_hsh[(size_t)MROWS * HH], g_hsl[(size_t)MROWS * HH];
__device__ __nv_bfloat16 g_wkh[CN * NS],  g_wkl[CN * NS];
__device__ __nv_bfloat16 g_wih[G4 * 2 * CN], g_wil[G4 * 2 * CN];
__device__ __nv_bfloat16 g_wsh[CN * HH],  g_wsl[CN * HH];

// ---- helpers ----
__device__ __forceinline__ void splitbf(float v, __nv_bfloat16& h, __nv_bfloat16& l) {
    h = __float2bfloat16_rn(v);
    l = __float2bfloat16_rn(v - __bfloat162float(h));
}
__device__ __forceinline__ uint32 smaddr(const void* p) {
    return (uint32)__cvta_generic_to_shared(p);
}
__device__ __forceinline__ void ldm4(uint32* r, uint32 addr) {
    asm volatile("ldmatrix.sync.aligned.m8n8.x4.shared.b16 {%0,%1,%2,%3}, [%4];"
                 : "=r"(r[0]), "=r"(r[1]), "=r"(r[2]), "=r"(r[3]) : "r"(addr));
}
__device__ __forceinline__ void mma16816(float* c, const uint32* a, const uint32* b) {
    asm volatile("mma.sync.aligned.m16n8k16.row.col.f32.bf16.bf16.f32 "
                 "{%0,%1,%2,%3},{%4,%5,%6,%7},{%8,%9},{%0,%1,%2,%3};"
                 : "+f"(c[0]), "+f"(c[1]), "+f"(c[2]), "+f"(c[3])
                 : "r"(a[0]), "r"(a[1]), "r"(a[2]), "r"(a[3]), "r"(b[0]), "r"(b[1]));
}

__global__ void init_misc() {
    int i = blockIdx.x * blockDim.x + threadIdx.x;
    if (i < 2 * FRAGW) ((uint32*)g_hfrag[0])[i] = 0u;   // zero buffer 0, both planes
    if (i == 0) g_barc = 0u;
}

// fp32 -> (hi, lo) bf16 planes
__global__ void cvt_split(const float* __restrict__ src,
                          __nv_bfloat16* __restrict__ hi,
                          __nv_bfloat16* __restrict__ lo, int n4) {
    int i = blockIdx.x * blockDim.x + threadIdx.x;
    if (i >= n4) return;
    float4 v = ((const float4*)src)[i];
    __nv_bfloat16 h, l;
    splitbf(v.x, h, l); hi[4*i+0] = h; lo[4*i+0] = l;
    splitbf(v.y, h, l); hi[4*i+1] = h; lo[4*i+1] = l;
    splitbf(v.z, h, l); hi[4*i+2] = h; lo[4*i+2] = l;
    splitbf(v.w, h, l); hi[4*i+3] = h; lo[4*i+3] = l;
}

// ---------------------------------------------------------------------------
// bf16-split tensor-core GEMM (unchanged, validated R3/R4)
// ---------------------------------------------------------------------------
__global__ __launch_bounds__(256, 1) void mma_gemm(
        const __nv_bfloat16* __restrict__ Ah_, const __nv_bfloat16* __restrict__ Al_,
        const __nv_bfloat16* __restrict__ Bh,  const __nv_bfloat16* __restrict__ Bl,
        const float* __restrict__ bias, const float* __restrict__ bias2,
        float* __restrict__ Cext, int M, int N, int K, int mode,
        const int* __restrict__ resm) {
    __shared__ __nv_bfloat16 sAh[128][40], sAl[128][40];
    __shared__ __nv_bfloat16 sBh[128][40], sBl[128][40];

    const __nv_bfloat16* Ah = Ah_;
    const __nv_bfloat16* Al = Al_;
    if (mode == 2)      { Ah = g_kcvh; Al = g_kcvl; }
    else if (mode == 3) { Ah = g_hsh;  Al = g_hsl; }

    const int tid = threadIdx.x;
    const int m0 = blockIdx.y * 128, n0 = blockIdx.x * 128;
    const int warp = tid >> 5, lane = tid & 31;
    const int wm = warp >> 1, wn = warp & 1;

    const int lrow = tid >> 1;
    const int lcol = (tid & 1) * 16;

    float acc[2][8][4];
#pragma unroll
    for (int i = 0; i < 2; i++)
#pragma unroll
        for (int j = 0; j < 8; j++)
#pragma unroll
            for (int q = 0; q < 4; q++) acc[i][j][q] = 0.f;

    for (int k0 = 0; k0 < K; k0 += 32) {
        uint4 ah0 = *(const uint4*)&Ah[(size_t)(m0 + lrow) * K + k0 + lcol];
        uint4 ah1 = *(const uint4*)&Ah[(size_t)(m0 + lrow) * K + k0 + lcol + 8];
        uint4 al0 = *(const uint4*)&Al[(size_t)(m0 + lrow) * K + k0 + lcol];
        uint4 al1 = *(const uint4*)&Al[(size_t)(m0 + lrow) * K + k0 + lcol + 8];
        uint4 bh0 = *(const uint4*)&Bh[(size_t)(n0 + lrow) * K + k0 + lcol];
        uint4 bh1 = *(const uint4*)&Bh[(size_t)(n0 + lrow) * K + k0 + lcol + 8];
        uint4 bl0 = *(const uint4*)&Bl[(size_t)(n0 + lrow) * K + k0 + lcol];
        uint4 bl1 = *(const uint4*)&Bl[(size_t)(n0 + lrow) * K + k0 + lcol + 8];
        __syncthreads();
        *(uint4*)&sAh[lrow][lcol] = ah0; *(uint4*)&sAh[lrow][lcol + 8] = ah1;
        *(uint4*)&sAl[lrow][lcol] = al0; *(uint4*)&sAl[lrow][lcol + 8] = al1;
        *(uint4*)&sBh[lrow][lcol] = bh0; *(uint4*)&sBh[lrow][lcol + 8] = bh1;
        *(uint4*)&sBl[lrow][lcol] = bl0; *(uint4*)&sBl[lrow][lcol + 8] = bl1;
        __syncthreads();

#pragma unroll
        for (int ks = 0; ks < 32; ks += 16) {
            uint32 aH[2][4], aL[2][4];
#pragma unroll
            for (int mt = 0; mt < 2; mt++) {
                int row = wm * 32 + mt * 16 + (lane & 15);
                int col = ks + (lane >> 4) * 8;
                ldm4(aH[mt], smaddr(&sAh[row][col]));
                ldm4(aL[mt], smaddr(&sAl[row][col]));
            }
            uint32 bH[8][2], bL[8][2];
#pragma unroll
            for (int np = 0; np < 4; np++) {
                int row = wn * 64 + np * 16 + (lane & 7) + ((lane >> 4) & 1) * 8;
                int col = ks + ((lane >> 3) & 1) * 8;
                uint32 t4[4];
                ldm4(t4, smaddr(&sBh[row][col]));
                bH[2*np][0] = t4[0]; bH[2*np][1] = t4[1];
                bH[2*np+1][0] = t4[2]; bH[2*np+1][1] = t4[3];
                ldm4(t4, smaddr(&sBl[row][col]));
                bL[2*np][0] = t4[0]; bL[2*np][1] = t4[1];
                bL[2*np+1][0] = t4[2]; bL[2*np+1][1] = t4[3];
            }
#pragma unroll
            for (int mt = 0; mt < 2; mt++)
#pragma unroll
                for (int nt = 0; nt < 8; nt++) {
                    mma16816(acc[mt][nt], aH[mt], bH[nt]);
                    mma16816(acc[mt][nt], aH[mt], bL[nt]);
                    mma16816(acc[mt][nt], aL[mt], bH[nt]);
                }
        }
    }

#pragma unroll
    for (int mt = 0; mt < 2; mt++) {
#pragma unroll
        for (int nt = 0; nt < 8; nt++) {
#pragma unroll
            for (int q = 0; q < 4; q++) {
                int m = m0 + wm * 32 + mt * 16 + (lane >> 2) + (q >> 1) * 8;
                int n = n0 + wn * 64 + nt * 8 + 2 * (lane & 3) + (q & 1);
                float v = acc[mt][nt][q] + bias[n];
                if (bias2) v += bias2[n];
                if (mode == 0) {
                    g_nextkc[m * CN + n] = v;
                } else if (mode == 1) {
                    float msk = (resm[m] == 1) ? 1.f : 0.f;
                    __nv_bfloat16 h, l;
                    splitbf(v * msk, h, l);
                    g_kcvh[(size_t)m * 2 * CN + n] = h;
                    g_kcvl[(size_t)m * 2 * CN + n] = l;
                    splitbf(v * (1.f - msk), h, l);
                    g_kcvh[(size_t)m * 2 * CN + CN + n] = h;
                    g_kcvl[(size_t)m * 2 * CN + CN + n] = l;
                } else if (mode == 2) {
                    int b = m / TT, t = m - b * TT;
                    g_G[((size_t)t * BB + b) * G4 + n] = v;
                } else {
                    Cext[(size_t)m * CN + n] = v;
                }
            }
        }
    }
}

// ---------------------------------------------------------------------------
// grid barrier
// ---------------------------------------------------------------------------
__device__ __forceinline__ void gsync(unsigned target) {
    __syncthreads();
    if (threadIdx.x == 0) {
        __threadfence();
        atomicAdd(&g_barc, 1u);
        unsigned v;
        do {
            asm volatile("ld.acquire.gpu.global.u32 %0, [%1];" : "=r"(v) : "l"(&g_barc));
        } while (v < target);
    }
    __syncthreads();
}

// ---------------------------------------------------------------------------
// Persistent fused LSTM, register-resident W_hh fragments.
// 128 CTAs; CTA k owns hidden units [8k,8k+8) -> 32 gate cols (N=32).
// Warp w owns K slice [128w, 128w+128): B frags (Whh) extracted ONCE into
// 128 regs; per step it LDGs h A-frags (fragment-layout global, coalesced),
// does 384 mma (3-product bf16 split), STS partials; warps 0-1 reduce + gates,
// scatter h back to fragment layout + linear hseq planes; grid barrier.
// ---------------------------------------------------------------------------
__global__ __launch_bounds__(256, 1) void lstm_persist(const float* __restrict__ Whh) {
    extern __shared__ char smraw[];
    __nv_bfloat16* whh_h = (__nv_bfloat16*)smraw;           // staging (init only)
    __nv_bfloat16* whh_l = whh_h + 32 * WHP;
    float* part = (float*)smraw;                             // [8][64][PSTR] after init

    const int tid = threadIdx.x, wid = tid >> 5, lane = tid & 31;
    const int jb0 = blockIdx.x * 8;

    // ---- stage Whh slice (hi/lo) into smem ----
    for (int idx = tid; idx < 32 * 1024; idx += 256) {
        int c = idx >> 10, k = idx & 1023;
        int gr = ((c >> 3) << 10) + jb0 + (c & 7);
        float w = Whh[(size_t)gr * HH + k];
        __nv_bfloat16 h, l;
        splitbf(w, h, l);
        whh_h[c * WHP + k] = h;
        whh_l[c * WHP + k] = l;
    }
    __syncthreads();

    // ---- extract B fragments into registers (persistent for all 200 steps) ----
    uint32 BH[8][4][2], BL[8][4][2];
#pragma unroll
    for (int kbl = 0; kbl < 8; kbl++) {
#pragma unroll
        for (int g = 0; g < 2; g++) {
            int row = g * 16 + (lane & 7) + ((lane >> 4) & 1) * 8;
            int col = (wid * 8 + kbl) * 16 + ((lane >> 3) & 1) * 8;
            uint32 t4[4];
            ldm4(t4, smaddr(&whh_h[row * WHP + col]));
            BH[kbl][2*g][0] = t4[0]; BH[kbl][2*g][1] = t4[1];
            BH[kbl][2*g+1][0] = t4[2]; BH[kbl][2*g+1][1] = t4[3];
            ldm4(t4, smaddr(&whh_l[row * WHP + col]));
            BL[kbl][2*g][0] = t4[0]; BL[kbl][2*g][1] = t4[1];
            BL[kbl][2*g+1][0] = t4[2]; BL[kbl][2*g+1][1] = t4[3];
        }
    }
    __syncthreads();   // staging area now reusable as partials

    // gate-thread constants (warps 0-1)
    const int b0 = (wid < 2) ? (wid * 32 + lane) : 0;
    const int m16w = b0 >> 4, roww = b0 & 15;
    const int rlw = roww & 7;
    const int regbase = (roww >> 3) + ((jb0 & 8) ? 2 : 0);
    const int k16w = jb0 >> 4;
    float cst[8];
#pragma unroll
    for (int u = 0; u < 8; u++) cst[u] = 0.f;

    for (int t = 0; t < TT; t++) {
        const uint32* fH = g_hfrag[t & 1][0];
        const uint32* fL = g_hfrag[t & 1][1];
        const int nb = (t + 1) & 1;

        float acc[4][4][4];
#pragma unroll
        for (int mf = 0; mf < 4; mf++)
#pragma unroll
            for (int nf = 0; nf < 4; nf++)
#pragma unroll
                for (int q = 0; q < 4; q++) acc[mf][nf][q] = 0.f;

#pragma unroll
        for (int kbl = 0; kbl < 8; kbl++) {
            const int kb = wid * 8 + kbl;
            uint4 aH4[4];
#pragma unroll
            for (int mf = 0; mf < 4; mf++)
                aH4[mf] = __ldcg((const uint4*)&fH[((kb * 4 + mf) * 32 + lane) * 4]);
#pragma unroll
            for (int mf = 0; mf < 4; mf++)
#pragma unroll
                for (int nf = 0; nf < 4; nf++) {
                    mma16816(acc[mf][nf], (const uint32*)&aH4[mf], BH[kbl][nf]);
                    mma16816(acc[mf][nf], (const uint32*)&aH4[mf], BL[kbl][nf]);
                }
            uint4 aL4[4];
#pragma unroll
            for (int mf = 0; mf < 4; mf++)
                aL4[mf] = __ldcg((const uint4*)&fL[((kb * 4 + mf) * 32 + lane) * 4]);
#pragma unroll
            for (int mf = 0; mf < 4; mf++)
#pragma unroll
                for (int nf = 0; nf < 4; nf++)
                    mma16816(acc[mf][nf], (const uint32*)&aL4[mf], BH[kbl][nf]);
        }

        // STS partials: part[wid][b][n]
        {
            float* pw = part + wid * (64 * PSTR);
            int rowc = lane >> 2, colc = (lane & 3) * 2;
#pragma unroll
            for (int mf = 0; mf < 4; mf++)
#pragma unroll
                for (int nf = 0; nf < 4; nf++) {
                    int n = nf * 8 + colc;
                    *(float2*)&pw[(mf * 16 + rowc) * PSTR + n] =
                        make_float2(acc[mf][nf][0], acc[mf][nf][1]);
                    *(float2*)&pw[(mf * 16 + rowc + 8) * PSTR + n] =
                        make_float2(acc[mf][nf][2], acc[mf][nf][3]);
                }
        }
        __syncthreads();

        // warps 0-1: reduce partials, gates, write h
        if (wid < 2) {
            float z[32];
#pragma unroll
            for (int n = 0; n < 32; n++) z[n] = 0.f;
#pragma unroll
            for (int w8 = 0; w8 < 8; w8++) {
                const float* pr = part + w8 * (64 * PSTR) + b0 * PSTR;
#pragma unroll
                for (int c4 = 0; c4 < 8; c4++) {
                    float4 v = *(const float4*)&pr[c4 * 4];
                    z[c4*4+0] += v.x; z[c4*4+1] += v.y; z[c4*4+2] += v.z; z[c4*4+3] += v.w;
                }
            }
            const float* Gp = g_G + ((size_t)t * BB + b0) * G4 + jb0;
            float gb[4][8];
#pragma unroll
            for (int g = 0; g < 4; g++) {
                float4 v0 = __ldcg((const float4*)&Gp[g * HH]);
                float4 v1 = __ldcg((const float4*)&Gp[g * HH + 4]);
                gb[g][0] = v0.x; gb[g][1] = v0.y; gb[g][2] = v0.z; gb[g][3] = v0.w;
                gb[g][4] = v1.x; gb[g][5] = v1.y; gb[g][6] = v1.z; gb[g][7] = v1.w;
            }
            unsigned short hh[8], hl[8];
#pragma unroll
            for (int u = 0; u < 8; u++) {
                float pi = z[u]      + gb[0][u];
                float pf = z[8 + u]  + gb[1][u];
                float pg = z[16 + u] + gb[2][u];
                float po = z[24 + u] + gb[3][u];
                float iv = 1.f / (1.f + expf(-pi));
                float fv = 1.f / (1.f + expf(-pf));
                float ov = 1.f / (1.f + expf(-po));
                float gv = tanhf(pg);
                cst[u] = fv * cst[u] + iv * gv;
                float h = ov * tanhf(cst[u]);
                __nv_bfloat16 bh, bl;
                splitbf(h, bh, bl);
                hh[u] = __bfloat16_as_ushort(bh);
                hl[u] = __bfloat16_as_ushort(bl);
            }
            // scatter into A-fragment layout: pair u -> cols 2u,2u+1
            uint32* dH = g_hfrag[nb][0];
            uint32* dL = g_hfrag[nb][1];
#pragma unroll
            for (int u = 0; u < 4; u++) {
                uint32 vh = (uint32)hh[2*u] | ((uint32)hh[2*u+1] << 16);
                uint32 vl = (uint32)hl[2*u] | ((uint32)hl[2*u+1] << 16);
                int idx = ((k16w * 4 + m16w) * 32 + rlw * 4 + u) * 4 + regbase;
                dH[idx] = vh;
                dL[idx] = vl;
            }
            // linear hseq planes for the state GEMM
            uint4 vh4, vl4;
            vh4.x = (uint32)hh[0] | ((uint32)hh[1] << 16);
            vh4.y = (uint32)hh[2] | ((uint32)hh[3] << 16);
            vh4.z = (uint32)hh[4] | ((uint32)hh[5] << 16);
            vh4.w = (uint32)hh[6] | ((uint32)hh[7] << 16);
            vl4.x = (uint32)hl[0] | ((uint32)hl[1] << 16);
            vl4.y = (uint32)hl[2] | ((uint32)hl[3] << 16);
            vl4.z = (uint32)hl[4] | ((uint32)hl[5] << 16);
            vl4.w = (uint32)hl[6] | ((uint32)hl[7] << 16);
            *(uint4*)&g_hsh[((size_t)b0 * TT + t) * HH + jb0] = vh4;
            *(uint4*)&g_hsl[((size_t)b0 * TT + t) * HH + jb0] = vl4;
        }

        gsync((unsigned)(t + 1) * NCTA);
    }
}

// ---------------------------------------------------------------------------
__global__ void out_kernel(const float* __restrict__ Wout,
                           const float* __restrict__ bout,
                           float* __restrict__ dout) {
    int gw = (blockIdx.x * blockDim.x + threadIdx.x) >> 5;
    int lane = threadIdx.x & 31;
    if (gw >= MROWS) return;
    const float* stu = dout + MROWS + (size_t)gw * CN;
    float s = 0.f;
#pragma unroll
    for (int c = lane; c < CN; c += 32) {
        float nk = g_nextkc[gw * CN + c];
        s += (stu[c] - nk) * nk * Wout[c];
    }
#pragma unroll
    for (int o = 16; o; o >>= 1) s += __shfl_down_sync(0xffffffffu, s, o);
    if (lane == 0) dout[gw] = s + bout[0];
}

extern "C" void kernel_launch(void* const* d_in, const int* in_sizes, int n_in,
                              void* d_out, int out_size) {
    int wi = (n_in >= 14) ? 4 : 3;
    const float* q_hot   = (const float*)d_in[0];
    const int*   result  = (const int*)  d_in[1];
    const float* next_q  = (const float*)d_in[2];
    const float* W_kc    = (const float*)d_in[wi + 0];
    const float* b_kc    = (const float*)d_in[wi + 1];
    const float* W_ih    = (const float*)d_in[wi + 2];
    const float* W_hh    = (const float*)d_in[wi + 3];
    const float* b_ih    = (const float*)d_in[wi + 4];
    const float* b_hh    = (const float*)d_in[wi + 5];
    const float* W_state = (const float*)d_in[wi + 6];
    const float* b_state = (const float*)d_in[wi + 7];
    const float* W_out   = (const float*)d_in[wi + 8];
    const float* b_out   = (const float*)d_in[wi + 9];
    float* out = (float*)d_out;

    static int smem_set = 0;
    if (!smem_set) {
        cudaFuncSetAttribute(lstm_persist, cudaFuncAttributeMaxDynamicSharedMemorySize, SMEM_LSTM);
        smem_set = 1;
    }

    init_misc<<<(2 * FRAGW + 255) / 256, 256>>>();

    __nv_bfloat16 *qh, *ql, *nqh, *nql, *wkh, *wkl, *wih, *wil, *wsh, *wsl;
    cudaGetSymbolAddress((void**)&qh,  g_qh);  cudaGetSymbolAddress((void**)&ql,  g_ql);
    cudaGetSymbolAddress((void**)&nqh, g_nqh); cudaGetSymbolAddress((void**)&nql, g_nql);
    cudaGetSymbolAddress((void**)&wkh, g_wkh); cudaGetSymbolAddress((void**)&wkl, g_wkl);
    cudaGetSymbolAddress((void**)&wih, g_wih); cudaGetSymbolAddress((void**)&wil, g_wil);
    cudaGetSymbolAddress((void**)&wsh, g_wsh); cudaGetSymbolAddress((void**)&wsl, g_wsl);

    int n4q = MROWS * NS / 4;
    cvt_split<<<(n4q + 255) / 256, 256>>>(q_hot, qh, ql, n4q);
    cvt_split<<<(n4q + 255) / 256, 256>>>(next_q, nqh, nql, n4q);
    int n4k = CN * NS / 4;
    cvt_split<<<(n4k + 255) / 256, 256>>>(W_kc, wkh, wkl, n4k);
    int n4i = G4 * 2 * CN / 4;
    cvt_split<<<(n4i + 255) / 256, 256>>>(W_ih, wih, wil, n4i);
    int n4s = CN * HH / 4;
    cvt_split<<<(n4s + 255) / 256, 256>>>(W_state, wsh, wsl, n4s);

    dim3 gk(CN / 128, MROWS / 128);       // (2, 100)
    mma_gemm<<<gk, 256>>>(qh, ql, wkh, wkl, b_kc, nullptr, nullptr,
                          MROWS, CN, NS, 1, result);
    mma_gemm<<<gk, 256>>>(nqh, nql, wkh, wkl, b_kc, nullptr, nullptr,
                          MROWS, CN, NS, 0, nullptr);
    dim3 gg(G4 / 128, MROWS / 128);       // (32, 100)
    mma_gemm<<<gg, 256>>>(nullptr, nullptr, wih, wil, b_ih, b_hh, nullptr,
                          MROWS, G4, 2 * CN, 2, nullptr);

    lstm_persist<<<NCTA, 256, SMEM_LSTM>>>(W_hh);

    mma_gemm<<<gk, 256>>>(nullptr, nullptr, wsh, wsl, b_state, nullptr,
                          out + MROWS, MROWS, CN, HH, 3, nullptr);
    out_kernel<<<(MROWS * 32 + 255) / 256, 256>>>(W_out, b_out, out);
}

// round 10
// speedup vs baseline: 4.0443x; 1.2018x over previous
#include <cuda_runtime.h>
#include <cuda_bf16.h>
#include <math.h>

typedef unsigned long long ull;
typedef unsigned uint32;

// Problem dims
#define BB 64
#define TT 200
#define NS 1024
#define CN 256
#define HH 1024
#define G4 4096
#define MROWS (BB*TT)   // 12800
#define MPAD 12928      // MROWS + 128 (group-boundary padding)

// Persistent-kernel config
#define NCTA 128
#define WHP 1032                 // Whh staging pitch (bf16)
#define PSTR 40                  // partial-sum row stride (floats)
#define SMEM_LSTM 132096         // max(whh staging 132096, partials 81920)
#define FRAGW 32768              // uint32 per plane per buffer

// ---- scratch globals (allocation-free) ----
__device__ float g_G[(size_t)MROWS * G4];          // [t][b][4096]
__device__ float g_nextkc[MROWS * CN];
__device__ uint32 g_hfrag[2][2][FRAGW];            // h in A-fragment layout [buf][plane]
__device__ unsigned g_barc;

// mask-sort tables
__device__ int g_perm[MROWS];    // original m -> permuted row
__device__ int g_inv[MPAD];      // permuted row -> original m (-1 = pad)
__device__ int g_n1pad;          // padded group-1 size (multiple of 128)

// bf16 split planes
__device__ __nv_bfloat16 g_qh[(size_t)MROWS * NS],  g_ql[(size_t)MROWS * NS];
__device__ __nv_bfloat16 g_nqh[(size_t)MROWS * NS], g_nql[(size_t)MROWS * NS];
__device__ __nv_bfloat16 g_pch[(size_t)MPAD * CN], g_pcl[(size_t)MPAD * CN];  // permuted kc planes
__device__ __nv_bfloat16 g_hsh[(size_t)MROWS * HH], g_hsl[(size_t)MROWS * HH];
__device__ __nv_bfloat16 g_wkh[CN * NS],  g_wkl[CN * NS];
__device__ __nv_bfloat16 g_wih[G4 * 2 * CN], g_wil[G4 * 2 * CN];
__device__ __nv_bfloat16 g_wsh[CN * HH],  g_wsl[CN * HH];

// ---- helpers ----
__device__ __forceinline__ void splitbf(float v, __nv_bfloat16& h, __nv_bfloat16& l) {
    h = __float2bfloat16_rn(v);
    l = __float2bfloat16_rn(v - __bfloat162float(h));
}
__device__ __forceinline__ uint32 smaddr(const void* p) {
    return (uint32)__cvta_generic_to_shared(p);
}
__device__ __forceinline__ void ldm4(uint32* r, uint32 addr) {
    asm volatile("ldmatrix.sync.aligned.m8n8.x4.shared.b16 {%0,%1,%2,%3}, [%4];"
                 : "=r"(r[0]), "=r"(r[1]), "=r"(r[2]), "=r"(r[3]) : "r"(addr));
}
__device__ __forceinline__ void mma16816(float* c, const uint32* a, const uint32* b) {
    asm volatile("mma.sync.aligned.m16n8k16.row.col.f32.bf16.bf16.f32 "
                 "{%0,%1,%2,%3},{%4,%5,%6,%7},{%8,%9},{%0,%1,%2,%3};"
                 : "+f"(c[0]), "+f"(c[1]), "+f"(c[2]), "+f"(c[3])
                 : "r"(a[0]), "r"(a[1]), "r"(a[2]), "r"(a[3]), "r"(b[0]), "r"(b[1]));
}

__global__ void init_misc() {
    int i = blockIdx.x * blockDim.x + threadIdx.x;
    if (i < 2 * FRAGW) ((uint32*)g_hfrag[0])[i] = 0u;
    if (i == 0) g_barc = 0u;
}

// mask-sort: stable partition rows by result==1, padded to 128-row boundary
__global__ void build_perm(const int* __restrict__ result) {
    __shared__ int s1[256];
    __shared__ int p1[256], p0[256];
    __shared__ int n1pad_s;
    int tid = threadIdx.x;
    for (int r = tid; r < MPAD; r += 256) g_inv[r] = -1;
    int base = tid * 50;
    int c1 = 0;
    for (int i = 0; i < 50; i++) c1 += (result[base + i] == 1);
    s1[tid] = c1;
    __syncthreads();
    if (tid == 0) {
        int a1 = 0, a0 = 0;
        for (int i = 0; i < 256; i++) {
            p1[i] = a1; a1 += s1[i];
            p0[i] = a0; a0 += 50 - s1[i];
        }
        n1pad_s = (a1 + 127) & ~127;
        g_n1pad = n1pad_s;
    }
    __syncthreads();
    int r1 = p1[tid], r0 = n1pad_s + p0[tid];
    for (int i = 0; i < 50; i++) {
        int m = base + i;
        int p = (result[m] == 1) ? r1++ : r0++;
        g_perm[m] = p;
        g_inv[p] = m;
    }
}

// fp32 -> (hi, lo) bf16 planes
__global__ void cvt_split(const float* __restrict__ src,
                          __nv_bfloat16* __restrict__ hi,
                          __nv_bfloat16* __restrict__ lo, int n4) {
    int i = blockIdx.x * blockDim.x + threadIdx.x;
    if (i >= n4) return;
    float4 v = ((const float4*)src)[i];
    __nv_bfloat16 h, l;
    splitbf(v.x, h, l); hi[4*i+0] = h; lo[4*i+0] = l;
    splitbf(v.y, h, l); hi[4*i+1] = h; lo[4*i+1] = l;
    splitbf(v.z, h, l); hi[4*i+2] = h; lo[4*i+2] = l;
    splitbf(v.w, h, l); hi[4*i+3] = h; lo[4*i+3] = l;
}

// ---------------------------------------------------------------------------
// bf16-split tensor-core GEMM.
// mode 0: C -> g_nextkc (fp32). mode 1: kc -> permuted planes g_pch/g_pcl.
// mode 2: A = permuted kc planes (K=256, lda=256), B = W_ih planes (ldb=512),
//         per-tile k-offset 0 (group 1) or 256 (group 0); scatter to g_G via g_inv.
// mode 3: A = hseq planes -> Cext fp32.
// ---------------------------------------------------------------------------
__global__ __launch_bounds__(256, 1) void mma_gemm(
        const __nv_bfloat16* __restrict__ Ah_, const __nv_bfloat16* __restrict__ Al_,
        const __nv_bfloat16* __restrict__ Bh_, const __nv_bfloat16* __restrict__ Bl_,
        const float* __restrict__ bias, const float* __restrict__ bias2,
        float* __restrict__ Cext, int K, int lda, int ldb, int mode) {
    __shared__ __nv_bfloat16 sAh[128][40], sAl[128][40];
    __shared__ __nv_bfloat16 sBh[128][40], sBl[128][40];

    const int tid = threadIdx.x;
    const int m0 = blockIdx.y * 128, n0 = blockIdx.x * 128;

    const __nv_bfloat16* Ah = Ah_;
    const __nv_bfloat16* Al = Al_;
    const __nv_bfloat16* Bh = Bh_;
    const __nv_bfloat16* Bl = Bl_;
    if (mode == 2) {
        Ah = g_pch; Al = g_pcl;
        int bofs = (m0 < g_n1pad) ? 0 : 256;   // W1 or W2 half of W_ih
        Bh += bofs; Bl += bofs;
    } else if (mode == 3) {
        Ah = g_hsh; Al = g_hsl;
    }

    const int warp = tid >> 5, lane = tid & 31;
    const int wm = warp >> 1, wn = warp & 1;
    const int lrow = tid >> 1;
    const int lcol = (tid & 1) * 16;

    float acc[2][8][4];
#pragma unroll
    for (int i = 0; i < 2; i++)
#pragma unroll
        for (int j = 0; j < 8; j++)
#pragma unroll
            for (int q = 0; q < 4; q++) acc[i][j][q] = 0.f;

    for (int k0 = 0; k0 < K; k0 += 32) {
        uint4 ah0 = *(const uint4*)&Ah[(size_t)(m0 + lrow) * lda + k0 + lcol];
        uint4 ah1 = *(const uint4*)&Ah[(size_t)(m0 + lrow) * lda + k0 + lcol + 8];
        uint4 al0 = *(const uint4*)&Al[(size_t)(m0 + lrow) * lda + k0 + lcol];
        uint4 al1 = *(const uint4*)&Al[(size_t)(m0 + lrow) * lda + k0 + lcol + 8];
        uint4 bh0 = *(const uint4*)&Bh[(size_t)(n0 + lrow) * ldb + k0 + lcol];
        uint4 bh1 = *(const uint4*)&Bh[(size_t)(n0 + lrow) * ldb + k0 + lcol + 8];
        uint4 bl0 = *(const uint4*)&Bl[(size_t)(n0 + lrow) * ldb + k0 + lcol];
        uint4 bl1 = *(const uint4*)&Bl[(size_t)(n0 + lrow) * ldb + k0 + lcol + 8];
        __syncthreads();
        *(uint4*)&sAh[lrow][lcol] = ah0; *(uint4*)&sAh[lrow][lcol + 8] = ah1;
        *(uint4*)&sAl[lrow][lcol] = al0; *(uint4*)&sAl[lrow][lcol + 8] = al1;
        *(uint4*)&sBh[lrow][lcol] = bh0; *(uint4*)&sBh[lrow][lcol + 8] = bh1;
        *(uint4*)&sBl[lrow][lcol] = bl0; *(uint4*)&sBl[lrow][lcol + 8] = bl1;
        __syncthreads();

#pragma unroll
        for (int ks = 0; ks < 32; ks += 16) {
            uint32 aH[2][4], aL[2][4];
#pragma unroll
            for (int mt = 0; mt < 2; mt++) {
                int row = wm * 32 + mt * 16 + (lane & 15);
                int col = ks + (lane >> 4) * 8;
                ldm4(aH[mt], smaddr(&sAh[row][col]));
                ldm4(aL[mt], smaddr(&sAl[row][col]));
            }
            uint32 bH[8][2], bL[8][2];
#pragma unroll
            for (int np = 0; np < 4; np++) {
                int row = wn * 64 + np * 16 + (lane & 7) + ((lane >> 4) & 1) * 8;
                int col = ks + ((lane >> 3) & 1) * 8;
                uint32 t4[4];
                ldm4(t4, smaddr(&sBh[row][col]));
                bH[2*np][0] = t4[0]; bH[2*np][1] = t4[1];
                bH[2*np+1][0] = t4[2]; bH[2*np+1][1] = t4[3];
                ldm4(t4, smaddr(&sBl[row][col]));
                bL[2*np][0] = t4[0]; bL[2*np][1] = t4[1];
                bL[2*np+1][0] = t4[2]; bL[2*np+1][1] = t4[3];
            }
#pragma unroll
            for (int mt = 0; mt < 2; mt++)
#pragma unroll
                for (int nt = 0; nt < 8; nt++) {
                    mma16816(acc[mt][nt], aH[mt], bH[nt]);
                    mma16816(acc[mt][nt], aH[mt], bL[nt]);
                    mma16816(acc[mt][nt], aL[mt], bH[nt]);
                }
        }
    }

#pragma unroll
    for (int mt = 0; mt < 2; mt++) {
#pragma unroll
        for (int nt = 0; nt < 8; nt++) {
#pragma unroll
            for (int q = 0; q < 4; q++) {
                int m = m0 + wm * 32 + mt * 16 + (lane >> 2) + (q >> 1) * 8;
                int n = n0 + wn * 64 + nt * 8 + 2 * (lane & 3) + (q & 1);
                float v = acc[mt][nt][q] + bias[n];
                if (bias2) v += bias2[n];
                if (mode == 0) {
                    g_nextkc[m * CN + n] = v;
                } else if (mode == 1) {
                    int pr = g_perm[m];
                    __nv_bfloat16 h, l;
                    splitbf(v, h, l);
                    g_pch[(size_t)pr * CN + n] = h;
                    g_pcl[(size_t)pr * CN + n] = l;
                } else if (mode == 2) {
                    int orig = g_inv[m];
                    if (orig >= 0) {
                        int b = orig / TT, t = orig - b * TT;
                        g_G[((size_t)t * BB + b) * G4 + n] = v;
                    }
                } else {
                    Cext[(size_t)m * CN + n] = v;
                }
            }
        }
    }
}

// ---------------------------------------------------------------------------
// grid barrier
// ---------------------------------------------------------------------------
__device__ __forceinline__ void gsync(unsigned target) {
    __syncthreads();
    if (threadIdx.x == 0) {
        __threadfence();
        atomicAdd(&g_barc, 1u);
        unsigned v;
        do {
            asm volatile("ld.acquire.gpu.global.u32 %0, [%1];" : "=r"(v) : "l"(&g_barc));
        } while (v < target);
    }
    __syncthreads();
}

// ---------------------------------------------------------------------------
// Persistent fused LSTM, register-resident W_hh fragments (R8 core) +
// gate phase parallelized over all 256 threads: thread = (b, j-pair).
// ---------------------------------------------------------------------------
__global__ __launch_bounds__(256, 1) void lstm_persist(const float* __restrict__ Whh) {
    extern __shared__ char smraw[];
    __nv_bfloat16* whh_h = (__nv_bfloat16*)smraw;           // staging (init only)
    __nv_bfloat16* whh_l = whh_h + 32 * WHP;
    float* part = (float*)smraw;                             // [8][64][PSTR] after init

    const int tid = threadIdx.x, wid = tid >> 5, lane = tid & 31;
    const int jb0 = blockIdx.x * 8;

    // ---- stage Whh slice (hi/lo) into smem ----
    for (int idx = tid; idx < 32 * 1024; idx += 256) {
        int c = idx >> 10, k = idx & 1023;
        int gr = ((c >> 3) << 10) + jb0 + (c & 7);
        float w = Whh[(size_t)gr * HH + k];
        __nv_bfloat16 h, l;
        splitbf(w, h, l);
        whh_h[c * WHP + k] = h;
        whh_l[c * WHP + k] = l;
    }
    __syncthreads();

    // ---- extract B fragments into registers (persistent) ----
    uint32 BH[8][4][2], BL[8][4][2];
#pragma unroll
    for (int kbl = 0; kbl < 8; kbl++) {
#pragma unroll
        for (int g = 0; g < 2; g++) {
            int row = g * 16 + (lane & 7) + ((lane >> 4) & 1) * 8;
            int col = (wid * 8 + kbl) * 16 + ((lane >> 3) & 1) * 8;
            uint32 t4[4];
            ldm4(t4, smaddr(&whh_h[row * WHP + col]));
            BH[kbl][2*g][0] = t4[0]; BH[kbl][2*g][1] = t4[1];
            BH[kbl][2*g+1][0] = t4[2]; BH[kbl][2*g+1][1] = t4[3];
            ldm4(t4, smaddr(&whh_l[row * WHP + col]));
            BL[kbl][2*g][0] = t4[0]; BL[kbl][2*g][1] = t4[1];
            BL[kbl][2*g+1][0] = t4[2]; BL[kbl][2*g+1][1] = t4[3];
        }
    }
    __syncthreads();   // staging area now reusable as partials

    // gate-thread constants: thread owns (b, j-pair {2jp, 2jp+1})
    const int gb_b = tid >> 2;          // 0..63
    const int gjp = tid & 3;            // 0..3
    const int m16w = gb_b >> 4;
    const int roww = gb_b & 15;
    const int rlw = roww & 7;
    const int regbase = (roww >> 3) + ((jb0 & 8) ? 2 : 0);
    const int k16w = jb0 >> 4;
    float cst2[2] = {0.f, 0.f};

    // G-bias prefetch for step 0
    float gb[4][2];
    {
        const float* Gp = g_G + (size_t)gb_b * G4 + jb0 + 2 * gjp;
#pragma unroll
        for (int g = 0; g < 4; g++) {
            float2 v = __ldcg((const float2*)&Gp[g * HH]);
            gb[g][0] = v.x; gb[g][1] = v.y;
        }
    }

    for (int t = 0; t < TT; t++) {
        const uint32* fH = g_hfrag[t & 1][0];
        const uint32* fL = g_hfrag[t & 1][1];
        const int nb = (t + 1) & 1;

        float acc[4][4][4];
#pragma unroll
        for (int mf = 0; mf < 4; mf++)
#pragma unroll
            for (int nf = 0; nf < 4; nf++)
#pragma unroll
                for (int q = 0; q < 4; q++) acc[mf][nf][q] = 0.f;

#pragma unroll
        for (int kbl = 0; kbl < 8; kbl++) {
            const int kb = wid * 8 + kbl;
            uint4 aH4[4];
#pragma unroll
            for (int mf = 0; mf < 4; mf++)
                aH4[mf] = __ldcg((const uint4*)&fH[((kb * 4 + mf) * 32 + lane) * 4]);
#pragma unroll
            for (int mf = 0; mf < 4; mf++)
#pragma unroll
                for (int nf = 0; nf < 4; nf++) {
                    mma16816(acc[mf][nf], (const uint32*)&aH4[mf], BH[kbl][nf]);
                    mma16816(acc[mf][nf], (const uint32*)&aH4[mf], BL[kbl][nf]);
                }
            uint4 aL4[4];
#pragma unroll
            for (int mf = 0; mf < 4; mf++)
                aL4[mf] = __ldcg((const uint4*)&fL[((kb * 4 + mf) * 32 + lane) * 4]);
#pragma unroll
            for (int mf = 0; mf < 4; mf++)
#pragma unroll
                for (int nf = 0; nf < 4; nf++)
                    mma16816(acc[mf][nf], (const uint32*)&aL4[mf], BH[kbl][nf]);
        }

        // STS partials: part[wid][b][n]
        {
            float* pw = part + wid * (64 * PSTR);
            int rowc = lane >> 2, colc = (lane & 3) * 2;
#pragma unroll
            for (int mf = 0; mf < 4; mf++)
#pragma unroll
                for (int nf = 0; nf < 4; nf++) {
                    int n = nf * 8 + colc;
                    *(float2*)&pw[(mf * 16 + rowc) * PSTR + n] =
                        make_float2(acc[mf][nf][0], acc[mf][nf][1]);
                    *(float2*)&pw[(mf * 16 + rowc + 8) * PSTR + n] =
                        make_float2(acc[mf][nf][2], acc[mf][nf][3]);
                }
        }
        __syncthreads();

        // gates: all 256 threads, thread = (gb_b, cols {2gjp, 2gjp+1} per gate)
        {
            float zz[4][2];
#pragma unroll
            for (int g = 0; g < 4; g++) { zz[g][0] = 0.f; zz[g][1] = 0.f; }
#pragma unroll
            for (int w8 = 0; w8 < 8; w8++) {
                const float* pr = part + w8 * (64 * PSTR) + gb_b * PSTR + 2 * gjp;
#pragma unroll
                for (int g = 0; g < 4; g++) {
                    float2 v = *(const float2*)&pr[g * 8];
                    zz[g][0] += v.x; zz[g][1] += v.y;
                }
            }
            unsigned short hh[2], hl[2];
#pragma unroll
            for (int e = 0; e < 2; e++) {
                float pi = zz[0][e] + gb[0][e];
                float pf = zz[1][e] + gb[1][e];
                float pg = zz[2][e] + gb[2][e];
                float po = zz[3][e] + gb[3][e];
                float iv = 1.f / (1.f + expf(-pi));
                float fv = 1.f / (1.f + expf(-pf));
                float ov = 1.f / (1.f + expf(-po));
                float gv = tanhf(pg);
                cst2[e] = fv * cst2[e] + iv * gv;
                float h = ov * tanhf(cst2[e]);
                __nv_bfloat16 bh, bl;
                splitbf(h, bh, bl);
                hh[e] = __bfloat16_as_ushort(bh);
                hl[e] = __bfloat16_as_ushort(bl);
            }
            uint32 vh = (uint32)hh[0] | ((uint32)hh[1] << 16);
            uint32 vl = (uint32)hl[0] | ((uint32)hl[1] << 16);
            // scatter into A-fragment layout (same formula as R8, u = gjp)
            int idx = ((k16w * 4 + m16w) * 32 + rlw * 4 + gjp) * 4 + regbase;
            g_hfrag[nb][0][idx] = vh;
            g_hfrag[nb][1][idx] = vl;
            // linear hseq planes
            *(uint32*)&g_hsh[((size_t)gb_b * TT + t) * HH + jb0 + 2 * gjp] = vh;
            *(uint32*)&g_hsl[((size_t)gb_b * TT + t) * HH + jb0 + 2 * gjp] = vl;
        }

        // prefetch next step's G biases (independent of barrier)
        if (t + 1 < TT) {
            const float* Gp = g_G + ((size_t)(t + 1) * BB + gb_b) * G4 + jb0 + 2 * gjp;
#pragma unroll
            for (int g = 0; g < 4; g++) {
                float2 v = __ldcg((const float2*)&Gp[g * HH]);
                gb[g][0] = v.x; gb[g][1] = v.y;
            }
        }

        gsync((unsigned)(t + 1) * NCTA);
    }
}

// ---------------------------------------------------------------------------
__global__ void out_kernel(const float* __restrict__ Wout,
                           const float* __restrict__ bout,
                           float* __restrict__ dout) {
    int gw = (blockIdx.x * blockDim.x + threadIdx.x) >> 5;
    int lane = threadIdx.x & 31;
    if (gw >= MROWS) return;
    const float* stu = dout + MROWS + (size_t)gw * CN;
    float s = 0.f;
#pragma unroll
    for (int c = lane; c < CN; c += 32) {
        float nk = g_nextkc[gw * CN + c];
        s += (stu[c] - nk) * nk * Wout[c];
    }
#pragma unroll
    for (int o = 16; o; o >>= 1) s += __shfl_down_sync(0xffffffffu, s, o);
    if (lane == 0) dout[gw] = s + bout[0];
}

extern "C" void kernel_launch(void* const* d_in, const int* in_sizes, int n_in,
                              void* d_out, int out_size) {
    int wi = (n_in >= 14) ? 4 : 3;
    const float* q_hot   = (const float*)d_in[0];
    const int*   result  = (const int*)  d_in[1];
    const float* next_q  = (const float*)d_in[2];
    const float* W_kc    = (const float*)d_in[wi + 0];
    const float* b_kc    = (const float*)d_in[wi + 1];
    const float* W_ih    = (const float*)d_in[wi + 2];
    const float* W_hh    = (const float*)d_in[wi + 3];
    const float* b_ih    = (const float*)d_in[wi + 4];
    const float* b_hh    = (const float*)d_in[wi + 5];
    const float* W_state = (const float*)d_in[wi + 6];
    const float* b_state = (const float*)d_in[wi + 7];
    const float* W_out   = (const float*)d_in[wi + 8];
    const float* b_out   = (const float*)d_in[wi + 9];
    float* out = (float*)d_out;

    static int smem_set = 0;
    if (!smem_set) {
        cudaFuncSetAttribute(lstm_persist, cudaFuncAttributeMaxDynamicSharedMemorySize, SMEM_LSTM);
        smem_set = 1;
    }

    init_misc<<<(2 * FRAGW + 255) / 256, 256>>>();
    build_perm<<<1, 256>>>(result);

    __nv_bfloat16 *qh, *ql, *nqh, *nql, *wkh, *wkl, *wih, *wil, *wsh, *wsl;
    cudaGetSymbolAddress((void**)&qh,  g_qh);  cudaGetSymbolAddress((void**)&ql,  g_ql);
    cudaGetSymbolAddress((void**)&nqh, g_nqh); cudaGetSymbolAddress((void**)&nql, g_nql);
    cudaGetSymbolAddress((void**)&wkh, g_wkh); cudaGetSymbolAddress((void**)&wkl, g_wkl);
    cudaGetSymbolAddress((void**)&wih, g_wih); cudaGetSymbolAddress((void**)&wil, g_wil);
    cudaGetSymbolAddress((void**)&wsh, g_wsh); cudaGetSymbolAddress((void**)&wsl, g_wsl);

    int n4q = MROWS * NS / 4;
    cvt_split<<<(n4q + 255) / 256, 256>>>(q_hot, qh, ql, n4q);
    cvt_split<<<(n4q + 255) / 256, 256>>>(next_q, nqh, nql, n4q);
    int n4k = CN * NS / 4;
    cvt_split<<<(n4k + 255) / 256, 256>>>(W_kc, wkh, wkl, n4k);
    int n4i = G4 * 2 * CN / 4;
    cvt_split<<<(n4i + 255) / 256, 256>>>(W_ih, wih, wil, n4i);
    int n4s = CN * HH / 4;
    cvt_split<<<(n4s + 255) / 256, 256>>>(W_state, wsh, wsl, n4s);

    dim3 gk(CN / 128, MROWS / 128);       // (2, 100)
    // kc -> permuted kc planes (mode 1)
    mma_gemm<<<gk, 256>>>(qh, ql, wkh, wkl, b_kc, nullptr, nullptr,
                          NS, NS, NS, 1);
    // next_kc (mode 0)
    mma_gemm<<<gk, 256>>>(nqh, nql, wkh, wkl, b_kc, nullptr, nullptr,
                          NS, NS, NS, 0);
    // gx (mode 2): permuted rows, K=256, per-tile W half, scatter via inv
    dim3 gg(G4 / 128, MPAD / 128);        // (32, 101)
    mma_gemm<<<gg, 256>>>(nullptr, nullptr, wih, wil, b_ih, b_hh, nullptr,
                          CN, CN, 2 * CN, 2);

    lstm_persist<<<NCTA, 256, SMEM_LSTM>>>(W_hh);

    // stu_state (mode 3)
    mma_gemm<<<gk, 256>>>(nullptr, nullptr, wsh, wsl, b_state, nullptr,
                          out + MROWS, HH, HH, HH, 3);
    out_kernel<<<(MROWS * 32 + 255) / 256, 256>>>(W_out, b_out, out);
}